// round 1
// baseline (speedup 1.0000x reference)
#include <cuda_runtime.h>
#include <math.h>
#include <stdint.h>

#define NN 100000
#define NE 3200000

// ---------------- device scratch (no allocations allowed) ----------------
__device__ float g_a[NN * 9];          // segment sums
__device__ float g_C112[45];           // [i*15 + j*5 + m]
__device__ float g_W222[125];          // [(a*5+b)*5+c]
__device__ float g_h0sum[128];
__device__ float g_h0sq[128];
__device__ float g_h1sq[192];          // per (v,m) slot
__device__ float g_h2sq[160];
__device__ __align__(16) float g_scale[480];
__device__ __align__(16) float g_bias[480];

// ---------------- zero scratch ----------------
__global__ void k_zero() {
    int i = blockIdx.x * blockDim.x + threadIdx.x;
    int stride = gridDim.x * blockDim.x;
    for (; i < NN * 9; i += stride) g_a[i] = 0.f;
    if (blockIdx.x == 0) {
        for (int j = threadIdx.x; j < 128; j += blockDim.x) { g_h0sum[j] = 0.f; g_h0sq[j] = 0.f; }
        for (int j = threadIdx.x; j < 192; j += blockDim.x) g_h1sq[j] = 0.f;
        for (int j = threadIdx.x; j < 160; j += blockDim.x) g_h2sq[j] = 0.f;
    }
}

// ---------------- constant tensors (C112, W222) ----------------
__global__ void k_init() {
    if (threadIdx.x != 0 || blockIdx.x != 0) return;
    float A[5][3][3];
    for (int m = 0; m < 5; m++)
        for (int i = 0; i < 3; i++)
            for (int j = 0; j < 3; j++) A[m][i][j] = 0.f;
    const float h = sqrtf(15.f) * 0.5f;
    const float s5 = sqrtf(5.f);
    A[0][0][2] = h; A[0][2][0] = h;
    A[1][0][1] = h; A[1][1][0] = h;
    A[2][0][0] = -0.5f * s5; A[2][1][1] = s5; A[2][2][2] = -0.5f * s5;
    A[3][1][2] = h; A[3][2][1] = h;
    A[4][0][0] = -h; A[4][2][2] = h;
    float ss = 0.f;
    for (int m = 0; m < 5; m++)
        for (int i = 0; i < 3; i++)
            for (int j = 0; j < 3; j++) ss += A[m][i][j] * A[m][i][j];
    float inv = 1.f / sqrtf(ss);
    for (int i = 0; i < 3; i++)
        for (int j = 0; j < 3; j++)
            for (int m = 0; m < 5; m++)
                g_C112[i * 15 + j * 5 + m] = A[m][i][j] * inv;
    // W[m,n,p] = sum_{i,k,j} A[m,i,k] A[n,k,j] A[p,j,i]; symmetrize in (m,n); normalize
    float Ws[5][5][5];
    float ss2 = 0.f;
    for (int m = 0; m < 5; m++)
        for (int n = 0; n < 5; n++)
            for (int p = 0; p < 5; p++) {
                float acc = 0.f, acc2 = 0.f;
                for (int i = 0; i < 3; i++)
                    for (int k = 0; k < 3; k++)
                        for (int j = 0; j < 3; j++) {
                            acc  += A[m][i][k] * A[n][k][j] * A[p][j][i];
                            acc2 += A[n][i][k] * A[m][k][j] * A[p][j][i];
                        }
                Ws[m][n][p] = acc + acc2;
                ss2 += (acc + acc2) * (acc + acc2);
            }
    float inv2 = 1.f / sqrtf(ss2);
    for (int m = 0; m < 5; m++)
        for (int n = 0; n < 5; n++)
            for (int p = 0; p < 5; p++)
                g_W222[(m * 5 + n) * 5 + p] = Ws[m][n][p] * inv2;
}

// ---------------- edge kernel ----------------
__global__ void __launch_bounds__(256) k_edge(
    const float* __restrict__ x, const float* __restrict__ pos,
    const int* __restrict__ ei,
    float* __restrict__ erbf, float* __restrict__ ersh)
{
    int e = blockIdx.x * blockDim.x + threadIdx.x;
    if (e >= NE) return;
    int s = ei[e];
    int t = ei[NE + e];
    // permuted pos: (pos[:,1], pos[:,2], pos[:,0])
    float vx = pos[3 * t + 1] - pos[3 * s + 1];
    float vy = pos[3 * t + 2] - pos[3 * s + 2];
    float vz = pos[3 * t + 0] - pos[3 * s + 0];
    float r2 = vx * vx + vy * vy + vz * vz;
    float r = sqrtf(r2);
    float inv = 1.f / fmaxf(r, 1e-12f);
    float ux = vx * inv, uy = vy * inv, uz = vz * inv;
    const float SQ3 = 1.7320508075688772f;
    const float SQ5 = 2.2360679774997896f;
    const float SQ15 = 3.8729833462074170f;
    float sh1 = SQ3 * ux, sh2 = SQ3 * uy, sh3 = SQ3 * uz;
    float sh4 = SQ15 * ux * uz;
    float sh5 = SQ15 * ux * uy;
    float sh6 = SQ5 * (uy * uy - 0.5f * (ux * ux + uz * uz));
    float sh7 = SQ15 * uy * uz;
    float sh8 = 0.5f * SQ15 * (uz * uz - ux * ux);
    float d = r * 0.1f;
    float d2 = d * d;
    float d5 = d2 * d2 * d;
    float fc = 1.f + d5 * (-21.f + d * (35.f - 15.f * d));
    fc = (d < 1.f) ? fc : 0.f;
    float ee = expf(-d2) * fc;
    float g0 = ee, g1 = d * ee, g2 = d2 * ee;

    const float* xs = x + 9 * (size_t)s;
    float* ga = g_a + 9 * (size_t)t;
    atomicAdd(ga + 0, xs[0] * g0);
    atomicAdd(ga + 1, xs[1] * sh1 * g1);
    atomicAdd(ga + 2, xs[2] * sh2 * g1);
    atomicAdd(ga + 3, xs[3] * sh3 * g1);
    atomicAdd(ga + 4, xs[4] * sh4 * g2);
    atomicAdd(ga + 5, xs[5] * sh5 * g2);
    atomicAdd(ga + 6, xs[6] * sh6 * g2);
    atomicAdd(ga + 7, xs[7] * sh7 * g2);
    atomicAdd(ga + 8, xs[8] * sh8 * g2);

    // erbf: sqrt(2/10)*sin(n*pi*r/10)/max(r,1e-12)*fc, n=1..16 via Chebyshev recurrence
    float sp, cp;
    sincosf(0.31415926535897931f * r, &sp, &cp);
    float coef = 0.44721359549995793f * inv * fc;
    float vals[16];
    float sprev = 0.f, scur = sp;
    float twoc = 2.f * cp;
#pragma unroll
    for (int n = 0; n < 16; n++) {
        vals[n] = coef * scur;
        float nx = twoc * scur - sprev;
        sprev = scur; scur = nx;
    }
    float4* ebp = (float4*)(erbf + 16 * (size_t)e);
    ebp[0] = make_float4(vals[0], vals[1], vals[2], vals[3]);
    ebp[1] = make_float4(vals[4], vals[5], vals[6], vals[7]);
    ebp[2] = make_float4(vals[8], vals[9], vals[10], vals[11]);
    ebp[3] = make_float4(vals[12], vals[13], vals[14], vals[15]);

    // ersh = sph_l012(-vec): l1 negated, l0/l2 even
    float* es = ersh + 9 * (size_t)e;
    es[0] = 1.f;
    es[1] = -sh1; es[2] = -sh2; es[3] = -sh3;
    es[4] = sh4; es[5] = sh5; es[6] = sh6; es[7] = sh7; es[8] = sh8;
}

// ---------------- node kernel ----------------
// shared layout (floats):
//   w0a[384] w1a[256] w2a[128] w0bT[128*132] w1bT[64*68] w2bT[32*36]
//   tpw[12] c112[48] w222[128] s[12] out[36] h0a[128] h1a[192] h2a[160]
#define SMEM_FLOATS 23884
#define SMEM_BYTES (SMEM_FLOATS * 4)

__device__ __forceinline__ float sigmoidf(float v) { return 1.f / (1.f + expf(-v)); }

__global__ void __launch_bounds__(128) k_node(
    const float* __restrict__ tp_w,
    const float* __restrict__ W0a, const float* __restrict__ W1a, const float* __restrict__ W2a,
    const float* __restrict__ W0b, const float* __restrict__ W1b, const float* __restrict__ W2b,
    float* __restrict__ out)
{
    extern __shared__ float sm[];
    float* w0a  = sm;            // 384
    float* w1a  = sm + 384;      // 256
    float* w2a  = sm + 640;      // 128
    float* w0bT = sm + 768;      // 16896 (rows of 132)
    float* w1bT = sm + 17664;    // 4352  (rows of 68)
    float* w2bT = sm + 22016;    // 1152  (rows of 36)
    float* tpw  = sm + 23168;    // 12
    float* c112 = sm + 23180;    // 48
    float* w222 = sm + 23228;    // 128
    float* s_sh = sm + 23356;    // 12
    float* out_sh = sm + 23368;  // 36
    float* h0a  = sm + 23404;    // 128
    float* h1a  = sm + 23532;    // 192
    float* h2a  = sm + 23724;    // 160

    int tid = threadIdx.x;
    for (int i = tid; i < 384; i += 128) w0a[i] = W0a[i];
    for (int i = tid; i < 256; i += 128) w1a[i] = W1a[i];
    if (tid < 128) w2a[tid] = W2a[tid];
    for (int i = tid; i < 16384; i += 128) { int k = i >> 7, f = i & 127; w0bT[f * 132 + k] = W0b[i]; }
    for (int i = tid; i < 4096;  i += 128) { int u = i >> 6, v = i & 63;  w1bT[v * 68 + u] = W1b[i]; }
    for (int i = tid; i < 1024;  i += 128) { int u = i >> 5, v = i & 31;  w2bT[v * 36 + u] = W2b[i]; }
    if (tid < 11)  tpw[tid] = tp_w[tid];
    if (tid < 45)  c112[tid] = g_C112[tid];
    if (tid < 125) w222[tid] = g_W222[tid];
    __syncthreads();

    float rs0 = 0.f, rq0 = 0.f, rq1a = 0.f, rq1b = 0.f, rq2a = 0.f, rq2b = 0.f;

    for (int n = blockIdx.x; n < NN; n += gridDim.x) {
        if (tid < 9) s_sh[tid] = g_a[n * 9 + tid];
        __syncthreads();

        if (tid < 35) {
            float s0 = s_sh[0];
            float val;
            if (tid == 0) {
                val = tpw[0] * s0 * s0;
            } else if (tid == 1) {
                float a = s_sh[1] * s_sh[1] + s_sh[2] * s_sh[2] + s_sh[3] * s_sh[3];
                val = tpw[1] * a * 0.57735026918962573f;
            } else if (tid == 2) {
                float a = 0.f;
                for (int m = 0; m < 5; m++) a += s_sh[4 + m] * s_sh[4 + m];
                val = tpw[2] * a * 0.44721359549995793f;
            } else if (tid < 6) {
                val = tpw[3] * s0 * s_sh[1 + (tid - 3)];
            } else if (tid < 9) {
                val = tpw[4] * s_sh[1 + (tid - 6)] * s0;
            } else if (tid < 12) {
                int j = tid - 9; float a = 0.f;
                for (int i = 0; i < 3; i++)
                    for (int m = 0; m < 5; m++)
                        a = fmaf(c112[i * 15 + j * 5 + m], s_sh[1 + i] * s_sh[4 + m], a);
                val = tpw[5] * a;
            } else if (tid < 15) {
                int i = tid - 12; float a = 0.f;
                for (int j = 0; j < 3; j++)
                    for (int m = 0; m < 5; m++)
                        a = fmaf(c112[i * 15 + j * 5 + m], s_sh[1 + j] * s_sh[4 + m], a);
                val = tpw[6] * a;
            } else if (tid < 20) {
                val = tpw[7] * s0 * s_sh[4 + (tid - 15)];
            } else if (tid < 25) {
                val = tpw[8] * s_sh[4 + (tid - 20)] * s0;
            } else if (tid < 30) {
                int m = tid - 25; float a = 0.f;
                for (int i = 0; i < 3; i++)
                    for (int j = 0; j < 3; j++)
                        a = fmaf(c112[i * 15 + j * 5 + m], s_sh[1 + i] * s_sh[1 + j], a);
                val = tpw[9] * a;
            } else {
                int c = tid - 30; float a = 0.f;
                for (int aa = 0; aa < 5; aa++)
                    for (int bb = 0; bb < 5; bb++)
                        a = fmaf(w222[(aa * 5 + bb) * 5 + c], s_sh[4 + aa] * s_sh[4 + bb], a);
                val = tpw[10] * a;
            }
            out_sh[tid] = val;  // [out0:0..2][out1:3..14][out2:15..34]
        }
        __syncthreads();

        // Stage A: h0a = sigmoid(out0 @ W0a); h1a,h2a gated
        {
            float o0 = out_sh[0], o1 = out_sh[1], o2 = out_sh[2];
            float hv = o0 * w0a[tid] + o1 * w0a[128 + tid] + o2 * w0a[256 + tid];
            h0a[tid] = sigmoidf(hv);
            if (tid < 64) {
                int v = tid;
                float m0 = 0.f, m1 = 0.f, m2 = 0.f;
#pragma unroll
                for (int u = 0; u < 4; u++) {
                    float w = w1a[u * 64 + v];
                    m0 = fmaf(out_sh[3 + u * 3 + 0], w, m0);
                    m1 = fmaf(out_sh[3 + u * 3 + 1], w, m1);
                    m2 = fmaf(out_sh[3 + u * 3 + 2], w, m2);
                }
                float gt = sigmoidf(sqrtf(m0 * m0 + m1 * m1 + m2 * m2));
                h1a[v * 3 + 0] = m0 * gt;
                h1a[v * 3 + 1] = m1 * gt;
                h1a[v * 3 + 2] = m2 * gt;
            } else if (tid < 96) {
                int v = tid - 64;
                float m[5] = {0.f, 0.f, 0.f, 0.f, 0.f};
#pragma unroll
                for (int u = 0; u < 4; u++) {
                    float w = w2a[u * 32 + v];
#pragma unroll
                    for (int mm = 0; mm < 5; mm++)
                        m[mm] = fmaf(out_sh[15 + u * 5 + mm], w, m[mm]);
                }
                float nrm = m[0]*m[0] + m[1]*m[1] + m[2]*m[2] + m[3]*m[3] + m[4]*m[4];
                float gt = sigmoidf(sqrtf(nrm));
#pragma unroll
                for (int mm = 0; mm < 5; mm++) h2a[v * 5 + mm] = m[mm] * gt;
            }
        }
        __syncthreads();

        float* op = out + (size_t)n * 480;

        // h0 @ W0b (feature tid)
        {
            const float4* wv = (const float4*)(w0bT + tid * 132);
            const float4* av = (const float4*)h0a;
            float a0 = 0.f, a1 = 0.f, a2 = 0.f, a3 = 0.f;
#pragma unroll
            for (int k = 0; k < 32; k += 4) {
                float4 w0 = wv[k],     b0 = av[k];
                float4 w1 = wv[k + 1], b1 = av[k + 1];
                float4 w2 = wv[k + 2], b2 = av[k + 2];
                float4 w3 = wv[k + 3], b3 = av[k + 3];
                a0 = fmaf(w0.x, b0.x, a0); a0 = fmaf(w0.y, b0.y, a0);
                a0 = fmaf(w0.z, b0.z, a0); a0 = fmaf(w0.w, b0.w, a0);
                a1 = fmaf(w1.x, b1.x, a1); a1 = fmaf(w1.y, b1.y, a1);
                a1 = fmaf(w1.z, b1.z, a1); a1 = fmaf(w1.w, b1.w, a1);
                a2 = fmaf(w2.x, b2.x, a2); a2 = fmaf(w2.y, b2.y, a2);
                a2 = fmaf(w2.z, b2.z, a2); a2 = fmaf(w2.w, b2.w, a2);
                a3 = fmaf(w3.x, b3.x, a3); a3 = fmaf(w3.y, b3.y, a3);
                a3 = fmaf(w3.z, b3.z, a3); a3 = fmaf(w3.w, b3.w, a3);
            }
            float hv = (a0 + a1) + (a2 + a3);
            op[tid] = hv;
            rs0 += hv; rq0 = fmaf(hv, hv, rq0);
        }

        // h1 @ W1b: slots o = tid, o = 128+tid (tid<64)
        {
            auto h1dot = [&](int o) -> float {
                int v = o / 3, m = o - 3 * v;
                const float* wr = w1bT + v * 68;
                float a0 = 0.f, a1 = 0.f;
#pragma unroll
                for (int u = 0; u < 64; u += 4) {
                    float4 w = *(const float4*)(wr + u);
                    a0 = fmaf(w.x, h1a[u * 3 + m],     a0);
                    a1 = fmaf(w.y, h1a[u * 3 + 3 + m], a1);
                    a0 = fmaf(w.z, h1a[u * 3 + 6 + m], a0);
                    a1 = fmaf(w.w, h1a[u * 3 + 9 + m], a1);
                }
                return a0 + a1;
            };
            float v1 = h1dot(tid);
            op[128 + tid] = v1;
            rq1a = fmaf(v1, v1, rq1a);
            if (tid < 64) {
                float v2 = h1dot(128 + tid);
                op[256 + tid] = v2;
                rq1b = fmaf(v2, v2, rq1b);
            }
        }

        // h2 @ W2b: slots o = tid, o = 128+tid (tid<32)
        {
            auto h2dot = [&](int o) -> float {
                int v = o / 5, m = o - 5 * v;
                const float* wr = w2bT + v * 36;
                float a0 = 0.f, a1 = 0.f;
#pragma unroll
                for (int u = 0; u < 32; u += 4) {
                    float4 w = *(const float4*)(wr + u);
                    a0 = fmaf(w.x, h2a[u * 5 + m],      a0);
                    a1 = fmaf(w.y, h2a[u * 5 + 5 + m],  a1);
                    a0 = fmaf(w.z, h2a[u * 5 + 10 + m], a0);
                    a1 = fmaf(w.w, h2a[u * 5 + 15 + m], a1);
                }
                return a0 + a1;
            };
            float v1 = h2dot(tid);
            op[320 + tid] = v1;
            rq2a = fmaf(v1, v1, rq2a);
            if (tid < 32) {
                float v2 = h2dot(128 + tid);
                op[448 + tid] = v2;
                rq2b = fmaf(v2, v2, rq2b);
            }
        }
        __syncthreads();
    }

    atomicAdd(&g_h0sum[tid], rs0);
    atomicAdd(&g_h0sq[tid], rq0);
    atomicAdd(&g_h1sq[tid], rq1a);
    if (tid < 64) atomicAdd(&g_h1sq[128 + tid], rq1b);
    atomicAdd(&g_h2sq[tid], rq2a);
    if (tid < 32) atomicAdd(&g_h2sq[128 + tid], rq2b);
}

// ---------------- scale/bias precompute ----------------
__global__ void k_scale() {
    int t = threadIdx.x;
    const float invN = 1.f / (float)NN;
    const float EPS = 1e-5f;
    if (t < 128) {
        float mean = g_h0sum[t] * invN;
        float var = g_h0sq[t] * invN - mean * mean;
        float sc = rsqrtf(var + EPS);
        g_scale[t] = sc;
        g_bias[t] = -mean * sc;
    } else if (t < 320) {
        int o = t - 128; int v = o / 3;
        float ms = (g_h1sq[3 * v] + g_h1sq[3 * v + 1] + g_h1sq[3 * v + 2]) * invN * (1.f / 3.f);
        g_scale[t] = rsqrtf(ms + EPS);
        g_bias[t] = 0.f;
    } else if (t < 480) {
        int o = t - 320; int v = o / 5;
        float ms = (g_h2sq[5 * v] + g_h2sq[5 * v + 1] + g_h2sq[5 * v + 2] +
                    g_h2sq[5 * v + 3] + g_h2sq[5 * v + 4]) * invN * 0.2f;
        g_scale[t] = rsqrtf(ms + EPS);
        g_bias[t] = 0.f;
    }
}

// ---------------- normalize node output in place ----------------
__global__ void __launch_bounds__(128) k_norm(float* __restrict__ out) {
    int t = threadIdx.x;
    if (t >= 120) return;
    float4 sc = *(const float4*)(g_scale + 4 * t);
    float4 bs = *(const float4*)(g_bias + 4 * t);
    for (int n = blockIdx.x; n < NN; n += gridDim.x) {
        float4* p = (float4*)(out + (size_t)n * 480) + t;
        float4 v = *p;
        v.x = fmaf(v.x, sc.x, bs.x);
        v.y = fmaf(v.y, sc.y, bs.y);
        v.z = fmaf(v.z, sc.z, bs.z);
        v.w = fmaf(v.w, sc.w, bs.w);
        *p = v;
    }
}

// ---------------- launch ----------------
extern "C" void kernel_launch(void* const* d_in, const int* in_sizes, int n_in,
                              void* d_out, int out_size) {
    const float* x   = (const float*)d_in[0];
    const float* pos = (const float*)d_in[1];
    const int*   ei  = (const int*)d_in[2];
    const float* tpw = (const float*)d_in[3];
    const float* W0a = (const float*)d_in[4];
    const float* W1a = (const float*)d_in[5];
    const float* W2a = (const float*)d_in[6];
    const float* W0b = (const float*)d_in[7];
    const float* W1b = (const float*)d_in[8];
    const float* W2b = (const float*)d_in[9];

    float* out  = (float*)d_out;
    float* erbf = out + (size_t)NN * 480;
    float* ersh = erbf + (size_t)NE * 16;

    cudaFuncSetAttribute(k_node, cudaFuncAttributeMaxDynamicSharedMemorySize, SMEM_BYTES);

    k_zero<<<512, 256>>>();
    k_init<<<1, 32>>>();
    k_edge<<<(NE + 255) / 256, 256>>>(x, pos, ei, erbf, ersh);
    k_node<<<296, 128, SMEM_BYTES>>>(tpw, W0a, W1a, W2a, W0b, W1b, W2b, out);
    k_scale<<<1, 512>>>();
    k_norm<<<1184, 128>>>(out);
}

// round 2
// speedup vs baseline: 1.2661x; 1.2661x over previous
#include <cuda_runtime.h>
#include <math.h>
#include <stdint.h>

#define NN 100000
#define NE 3200000
#define NTILES 3125   // NN / 32

typedef unsigned long long ull;

// ---------------- device scratch ----------------
__device__ float g_a[NN * 12];         // segment sums, padded stride 12 (16B aligned)
__device__ float g_xp[NN * 12];        // padded x
__device__ float4 g_pos4[NN];          // permuted pos
__device__ float g_C112[45];
__device__ float g_W222[125];
__device__ float g_h0sum[128];
__device__ float g_h0sq[128];
__device__ float g_h1sq[192];
__device__ float g_h2sq[160];
__device__ __align__(16) float g_scale[480];
__device__ __align__(16) float g_bias[480];

// ---------------- f32x2 helpers ----------------
__device__ __forceinline__ ull pack2(float a, float b) {
    ull r; asm("mov.b64 %0, {%1,%2};" : "=l"(r) : "f"(a), "f"(b)); return r;
}
__device__ __forceinline__ void fma2(ull& d, ull a, ull b) {
    asm("fma.rn.f32x2 %0, %1, %2, %0;" : "+l"(d) : "l"(a), "l"(b));
}
__device__ __forceinline__ void unpack2(ull v, float& a, float& b) {
    asm("mov.b64 {%0,%1}, %2;" : "=f"(a), "=f"(b) : "l"(v));
}
__device__ __forceinline__ float fsigmoid(float x) {
    return __fdividef(1.f, 1.f + __expf(-x));
}

// ---------------- zero scratch ----------------
__global__ void k_zero() {
    int i = blockIdx.x * blockDim.x + threadIdx.x;
    int stride = gridDim.x * blockDim.x;
    for (; i < NN * 12; i += stride) g_a[i] = 0.f;
    if (blockIdx.x == 0) {
        for (int j = threadIdx.x; j < 128; j += blockDim.x) { g_h0sum[j] = 0.f; g_h0sq[j] = 0.f; }
        for (int j = threadIdx.x; j < 192; j += blockDim.x) g_h1sq[j] = 0.f;
        for (int j = threadIdx.x; j < 160; j += blockDim.x) g_h2sq[j] = 0.f;
    }
}

// ---------------- constant tensors ----------------
__global__ void k_init() {
    if (threadIdx.x != 0 || blockIdx.x != 0) return;
    float A[5][3][3];
    for (int m = 0; m < 5; m++)
        for (int i = 0; i < 3; i++)
            for (int j = 0; j < 3; j++) A[m][i][j] = 0.f;
    const float h = sqrtf(15.f) * 0.5f;
    const float s5 = sqrtf(5.f);
    A[0][0][2] = h; A[0][2][0] = h;
    A[1][0][1] = h; A[1][1][0] = h;
    A[2][0][0] = -0.5f * s5; A[2][1][1] = s5; A[2][2][2] = -0.5f * s5;
    A[3][1][2] = h; A[3][2][1] = h;
    A[4][0][0] = -h; A[4][2][2] = h;
    float ss = 0.f;
    for (int m = 0; m < 5; m++)
        for (int i = 0; i < 3; i++)
            for (int j = 0; j < 3; j++) ss += A[m][i][j] * A[m][i][j];
    float inv = 1.f / sqrtf(ss);
    for (int i = 0; i < 3; i++)
        for (int j = 0; j < 3; j++)
            for (int m = 0; m < 5; m++)
                g_C112[i * 15 + j * 5 + m] = A[m][i][j] * inv;
    float Ws[5][5][5];
    float ss2 = 0.f;
    for (int m = 0; m < 5; m++)
        for (int n = 0; n < 5; n++)
            for (int p = 0; p < 5; p++) {
                float acc = 0.f, acc2 = 0.f;
                for (int i = 0; i < 3; i++)
                    for (int k = 0; k < 3; k++)
                        for (int j = 0; j < 3; j++) {
                            acc  += A[m][i][k] * A[n][k][j] * A[p][j][i];
                            acc2 += A[n][i][k] * A[m][k][j] * A[p][j][i];
                        }
                Ws[m][n][p] = acc + acc2;
                ss2 += (acc + acc2) * (acc + acc2);
            }
    float inv2 = 1.f / sqrtf(ss2);
    for (int m = 0; m < 5; m++)
        for (int n = 0; n < 5; n++)
            for (int p = 0; p < 5; p++)
                g_W222[(m * 5 + n) * 5 + p] = Ws[m][n][p] * inv2;
}

// ---------------- prep: pad x, permute pos ----------------
__global__ void k_prep(const float* __restrict__ x, const float* __restrict__ pos) {
    int n = blockIdx.x * blockDim.x + threadIdx.x;
    if (n >= NN) return;
    float4 p;
    p.x = pos[3 * n + 1]; p.y = pos[3 * n + 2]; p.z = pos[3 * n + 0]; p.w = 0.f;
    g_pos4[n] = p;
    const float* xs = x + 9 * (size_t)n;
    float4* xp = (float4*)(g_xp + 12 * (size_t)n);
    xp[0] = make_float4(xs[0], xs[1], xs[2], xs[3]);
    xp[1] = make_float4(xs[4], xs[5], xs[6], xs[7]);
    xp[2] = make_float4(xs[8], 0.f, 0.f, 0.f);
}

// ---------------- edge kernel ----------------
__global__ void __launch_bounds__(256) k_edge(
    const int* __restrict__ ei,
    float* __restrict__ erbf, float* __restrict__ ersh)
{
    int e = blockIdx.x * blockDim.x + threadIdx.x;
    if (e >= NE) return;
    int s = ei[e];
    int t = ei[NE + e];
    float4 ps = g_pos4[s], pt = g_pos4[t];
    float vx = pt.x - ps.x, vy = pt.y - ps.y, vz = pt.z - ps.z;
    float r2 = vx * vx + vy * vy + vz * vz;
    float r = sqrtf(r2);
    float inv = __fdividef(1.f, fmaxf(r, 1e-12f));
    float ux = vx * inv, uy = vy * inv, uz = vz * inv;
    const float SQ3 = 1.7320508075688772f;
    const float SQ5 = 2.2360679774997896f;
    const float SQ15 = 3.8729833462074170f;
    float sh1 = SQ3 * ux, sh2 = SQ3 * uy, sh3 = SQ3 * uz;
    float sh4 = SQ15 * ux * uz;
    float sh5 = SQ15 * ux * uy;
    float sh6 = SQ5 * (uy * uy - 0.5f * (ux * ux + uz * uz));
    float sh7 = SQ15 * uy * uz;
    float sh8 = 0.5f * SQ15 * (uz * uz - ux * ux);
    float d = r * 0.1f;
    float d2 = d * d;
    float d5 = d2 * d2 * d;
    float fc = 1.f + d5 * (-21.f + d * (35.f - 15.f * d));
    fc = (d < 1.f) ? fc : 0.f;
    float ee = __expf(-d2) * fc;
    float g0 = ee, g1 = d * ee, g2 = d2 * ee;

    const float4* xp = (const float4*)(g_xp + 12 * (size_t)s);
    float4 xa = xp[0], xb = xp[1];
    float x8 = g_xp[12 * (size_t)s + 8];

    float* ga = g_a + 12 * (size_t)t;
    float m0 = xa.x * g0;
    float m1 = xa.y * sh1 * g1;
    float m2 = xa.z * sh2 * g1;
    float m3 = xa.w * sh3 * g1;
    float m4 = xb.x * sh4 * g2;
    float m5 = xb.y * sh5 * g2;
    float m6 = xb.z * sh6 * g2;
    float m7 = xb.w * sh7 * g2;
    float m8 = x8   * sh8 * g2;
    asm volatile("red.global.add.v4.f32 [%0], {%1,%2,%3,%4};"
                 :: "l"(ga), "f"(m0), "f"(m1), "f"(m2), "f"(m3) : "memory");
    asm volatile("red.global.add.v4.f32 [%0], {%1,%2,%3,%4};"
                 :: "l"(ga + 4), "f"(m4), "f"(m5), "f"(m6), "f"(m7) : "memory");
    atomicAdd(ga + 8, m8);

    // erbf via sin recurrence
    float sp, cp;
    __sincosf(0.31415926535897931f * r, &sp, &cp);
    float coef = 0.44721359549995793f * inv * fc;
    float vals[16];
    float sprev = 0.f, scur = sp;
    float twoc = 2.f * cp;
#pragma unroll
    for (int n = 0; n < 16; n++) {
        vals[n] = coef * scur;
        float nx = twoc * scur - sprev;
        sprev = scur; scur = nx;
    }
    float4* ebp = (float4*)(erbf + 16 * (size_t)e);
    ebp[0] = make_float4(vals[0], vals[1], vals[2], vals[3]);
    ebp[1] = make_float4(vals[4], vals[5], vals[6], vals[7]);
    ebp[2] = make_float4(vals[8], vals[9], vals[10], vals[11]);
    ebp[3] = make_float4(vals[12], vals[13], vals[14], vals[15]);

    float* es = ersh + 9 * (size_t)e;
    es[0] = 1.f;
    es[1] = -sh1; es[2] = -sh2; es[3] = -sh3;
    es[4] = sh4; es[5] = sh5; es[6] = sh6; es[7] = sh7; es[8] = sh8;
}

// ---------------- node kernel: tiled (32 nodes) GEMM with f32x2 ----------------
// shared layout (floats)
#define SM_W0A   0        // 384
#define SM_W1A   384      // 256
#define SM_W2A   640      // 128
#define SM_W0B   768      // 16384 [k][f]
#define SM_W1B   17152    // 4096  [u][v]
#define SM_W2B   21248    // 1024  [u][v]
#define SM_TPW   22272    // 12
#define SM_C112  22284    // 48
#define SM_W222  22332    // 128
#define SM_S     22460    // 32*13 = 416
#define SM_OUTT  22876    // 35*32 = 1120
#define SM_H0    23996    // 128*32 = 4096
#define SM_H1    28092    // 192*32 = 6144
#define SM_H2    34236    // 160*32 = 5120
#define SMEM_FLOATS 39356
#define SMEM_BYTES (SMEM_FLOATS * 4)

template<int NU, int WS, int AS>
__device__ __forceinline__ void gemv_tile(
    const float* __restrict__ wp, const float* __restrict__ ab,
    float* __restrict__ op, float& osum, float& osq)
{
    ull a0 = 0, a1 = 0, a2 = 0, a3 = 0, a4 = 0, a5 = 0, a6 = 0, a7 = 0;
#pragma unroll 4
    for (int u = 0; u < NU; u++) {
        float w = wp[u * WS];
        ull w2 = pack2(w, w);
        const ulonglong2* a = (const ulonglong2*)(ab + u * AS);
        ulonglong2 q0 = a[0], q1 = a[1], q2 = a[2], q3 = a[3];
        fma2(a0, w2, q0.x); fma2(a1, w2, q0.y);
        fma2(a2, w2, q1.x); fma2(a3, w2, q1.y);
        fma2(a4, w2, q2.x); fma2(a5, w2, q2.y);
        fma2(a6, w2, q3.x); fma2(a7, w2, q3.y);
    }
    ull accs[8] = {a0, a1, a2, a3, a4, a5, a6, a7};
#pragma unroll
    for (int i = 0; i < 8; i++) {
        float y0, y1;
        unpack2(accs[i], y0, y1);
        op[(size_t)(2 * i) * 480] = y0;
        op[(size_t)(2 * i + 1) * 480] = y1;
        osum += y0 + y1;
        osq = fmaf(y0, y0, osq);
        osq = fmaf(y1, y1, osq);
    }
}

__global__ void __launch_bounds__(256) k_node(
    const float* __restrict__ tp_w,
    const float* __restrict__ W0a, const float* __restrict__ W1a, const float* __restrict__ W2a,
    const float* __restrict__ W0b, const float* __restrict__ W1b, const float* __restrict__ W2b,
    float* __restrict__ out)
{
    extern __shared__ float sm[];
    float* w0a  = sm + SM_W0A;
    float* w1a  = sm + SM_W1A;
    float* w2a  = sm + SM_W2A;
    float* w0b  = sm + SM_W0B;
    float* w1b  = sm + SM_W1B;
    float* w2b  = sm + SM_W2B;
    float* tpw  = sm + SM_TPW;
    float* c112 = sm + SM_C112;
    float* w222 = sm + SM_W222;
    float* s_sh = sm + SM_S;     // stride 13 per node
    float* out_t = sm + SM_OUTT; // [q][32]
    float* h0aT = sm + SM_H0;    // [k][32]
    float* h1aT = sm + SM_H1;    // [(v*3+m)][32]
    float* h2aT = sm + SM_H2;    // [(v*5+m)][32]

    const int tid = threadIdx.x;
    for (int i = tid; i < 384; i += 256) w0a[i] = W0a[i];
    if (tid < 256) w1a[tid] = W1a[tid];
    if (tid < 128) w2a[tid] = W2a[tid];
    for (int i = tid; i < 16384; i += 256) w0b[i] = W0b[i];
    for (int i = tid; i < 4096;  i += 256) w1b[i] = W1b[i];
    for (int i = tid; i < 1024;  i += 256) w2b[i] = W2b[i];
    if (tid < 11)  tpw[tid]  = tp_w[tid];
    if (tid < 45)  c112[tid] = g_C112[tid];
    if (tid < 125) w222[tid] = g_W222[tid];
    __syncthreads();

    // per-thread fixed slot descriptors
    const int f0  = tid & 127;
    const int nh0 = tid >> 7;
    const int o1a = (tid < 192) ? tid : tid - 192;
    const int nh1a = (tid < 192) ? 0 : 1;
    const int v1a = o1a / 3, m1a = o1a - 3 * v1a;
    const int o1b = 64 + tid;               // valid if tid < 128, nh = 1
    const int v1b = o1b / 3, m1b = o1b - 3 * v1b;
    const int o2a = (tid < 160) ? tid : tid - 160;
    const int nh2a = (tid < 160) ? 0 : 1;
    const int v2a = o2a / 5, m2a = o2a - 5 * v2a;
    const int o2b = 96 + tid;               // valid if tid < 64, nh = 1
    const int v2b = o2b / 5, m2b = o2b - 5 * v2b;

    float rs0 = 0.f, rq0 = 0.f, rq1a = 0.f, rq1b = 0.f, rq2a = 0.f, rq2b = 0.f;
    float dum = 0.f;

    for (int tile = blockIdx.x; tile < NTILES; tile += gridDim.x) {
        const int n0 = tile * 32;

        // load s for 32 nodes (3 float4 per node)
        if (tid < 96) {
            int n = tid / 3;
            int c = tid - 3 * n;
            const float4* gp = (const float4*)(g_a + (size_t)(n0 + n) * 12);
            float4 v = gp[c];
            float* dst = s_sh + n * 13 + c * 4;
            dst[0] = v.x; dst[1] = v.y; dst[2] = v.z; dst[3] = v.w;
        }
        __syncthreads();

        // tensor products -> out_t[q][n]
        for (int slot = tid; slot < 1120; slot += 256) {
            int q = slot >> 5, n = slot & 31;
            const float* s = s_sh + n * 13;
            float s0 = s[0];
            float val;
            if (q == 0) {
                val = tpw[0] * s0 * s0;
            } else if (q == 1) {
                float a = s[1] * s[1] + s[2] * s[2] + s[3] * s[3];
                val = tpw[1] * a * 0.57735026918962573f;
            } else if (q == 2) {
                float a = 0.f;
#pragma unroll
                for (int m = 0; m < 5; m++) a = fmaf(s[4 + m], s[4 + m], a);
                val = tpw[2] * a * 0.44721359549995793f;
            } else if (q < 6) {
                val = tpw[3] * s0 * s[1 + (q - 3)];
            } else if (q < 9) {
                val = tpw[4] * s[1 + (q - 6)] * s0;
            } else if (q < 12) {
                int j = q - 9; float a = 0.f;
#pragma unroll
                for (int i = 0; i < 3; i++)
#pragma unroll
                    for (int m = 0; m < 5; m++)
                        a = fmaf(c112[i * 15 + j * 5 + m], s[1 + i] * s[4 + m], a);
                val = tpw[5] * a;
            } else if (q < 15) {
                int i = q - 12; float a = 0.f;
#pragma unroll
                for (int j = 0; j < 3; j++)
#pragma unroll
                    for (int m = 0; m < 5; m++)
                        a = fmaf(c112[i * 15 + j * 5 + m], s[1 + j] * s[4 + m], a);
                val = tpw[6] * a;
            } else if (q < 20) {
                val = tpw[7] * s0 * s[4 + (q - 15)];
            } else if (q < 25) {
                val = tpw[8] * s[4 + (q - 20)] * s0;
            } else if (q < 30) {
                int m = q - 25; float a = 0.f;
#pragma unroll
                for (int i = 0; i < 3; i++)
#pragma unroll
                    for (int j = 0; j < 3; j++)
                        a = fmaf(c112[i * 15 + j * 5 + m], s[1 + i] * s[1 + j], a);
                val = tpw[9] * a;
            } else {
                int c = q - 30; float a = 0.f;
#pragma unroll
                for (int aa = 0; aa < 5; aa++)
#pragma unroll
                    for (int bb = 0; bb < 5; bb++)
                        a = fmaf(w222[(aa * 5 + bb) * 5 + c], s[4 + aa] * s[4 + bb], a);
                val = tpw[10] * a;
            }
            out_t[q * 32 + n] = val;
        }
        __syncthreads();

        // stage A
        for (int slot = tid; slot < 4096; slot += 256) {
            int f = slot >> 5, n = slot & 31;
            float hv = out_t[n] * w0a[f] + out_t[32 + n] * w0a[128 + f] + out_t[64 + n] * w0a[256 + f];
            h0aT[f * 32 + n] = fsigmoid(hv);
        }
        for (int slot = tid; slot < 2048; slot += 256) {
            int v = slot >> 5, n = slot & 31;
            float m0 = 0.f, m1 = 0.f, m2 = 0.f;
#pragma unroll
            for (int u = 0; u < 4; u++) {
                float w = w1a[u * 64 + v];
                m0 = fmaf(out_t[(3 + u * 3 + 0) * 32 + n], w, m0);
                m1 = fmaf(out_t[(3 + u * 3 + 1) * 32 + n], w, m1);
                m2 = fmaf(out_t[(3 + u * 3 + 2) * 32 + n], w, m2);
            }
            float gt = fsigmoid(sqrtf(m0 * m0 + m1 * m1 + m2 * m2));
            h1aT[(v * 3 + 0) * 32 + n] = m0 * gt;
            h1aT[(v * 3 + 1) * 32 + n] = m1 * gt;
            h1aT[(v * 3 + 2) * 32 + n] = m2 * gt;
        }
        for (int slot = tid; slot < 1024; slot += 256) {
            int v = slot >> 5, n = slot & 31;
            float m[5] = {0.f, 0.f, 0.f, 0.f, 0.f};
#pragma unroll
            for (int u = 0; u < 4; u++) {
                float w = w2a[u * 32 + v];
#pragma unroll
                for (int mm = 0; mm < 5; mm++)
                    m[mm] = fmaf(out_t[(15 + u * 5 + mm) * 32 + n], w, m[mm]);
            }
            float nrm = m[0]*m[0] + m[1]*m[1] + m[2]*m[2] + m[3]*m[3] + m[4]*m[4];
            float gt = fsigmoid(sqrtf(nrm));
#pragma unroll
            for (int mm = 0; mm < 5; mm++) h2aT[(v * 5 + mm) * 32 + n] = m[mm] * gt;
        }
        __syncthreads();

        // stage B GEMMs
        float* ob = out + (size_t)n0 * 480;
        gemv_tile<128, 128, 32>(w0b + f0, h0aT + nh0 * 16,
                                ob + (size_t)(nh0 * 16) * 480 + f0, rs0, rq0);
        gemv_tile<64, 64, 96>(w1b + v1a, h1aT + m1a * 32 + nh1a * 16,
                              ob + (size_t)(nh1a * 16) * 480 + 128 + o1a, dum, rq1a);
        if (tid < 128)
            gemv_tile<64, 64, 96>(w1b + v1b, h1aT + m1b * 32 + 16,
                                  ob + (size_t)16 * 480 + 128 + o1b, dum, rq1b);
        gemv_tile<32, 32, 160>(w2b + v2a, h2aT + m2a * 32 + nh2a * 16,
                               ob + (size_t)(nh2a * 16) * 480 + 320 + o2a, dum, rq2a);
        if (tid < 64)
            gemv_tile<32, 32, 160>(w2b + v2b, h2aT + m2b * 32 + 16,
                                   ob + (size_t)16 * 480 + 320 + o2b, dum, rq2b);
        __syncthreads();
    }

    atomicAdd(&g_h0sum[f0], rs0);
    atomicAdd(&g_h0sq[f0], rq0);
    atomicAdd(&g_h1sq[o1a], rq1a);
    if (tid < 128) atomicAdd(&g_h1sq[o1b], rq1b);
    atomicAdd(&g_h2sq[o2a], rq2a);
    if (tid < 64) atomicAdd(&g_h2sq[o2b], rq2b);
}

// ---------------- scale/bias precompute ----------------
__global__ void k_scale() {
    int t = threadIdx.x;
    const float invN = 1.f / (float)NN;
    const float EPS = 1e-5f;
    if (t < 128) {
        float mean = g_h0sum[t] * invN;
        float var = g_h0sq[t] * invN - mean * mean;
        float sc = rsqrtf(var + EPS);
        g_scale[t] = sc;
        g_bias[t] = -mean * sc;
    } else if (t < 320) {
        int o = t - 128; int v = o / 3;
        float ms = (g_h1sq[3 * v] + g_h1sq[3 * v + 1] + g_h1sq[3 * v + 2]) * invN * (1.f / 3.f);
        g_scale[t] = rsqrtf(ms + EPS);
        g_bias[t] = 0.f;
    } else if (t < 480) {
        int o = t - 320; int v = o / 5;
        float ms = (g_h2sq[5 * v] + g_h2sq[5 * v + 1] + g_h2sq[5 * v + 2] +
                    g_h2sq[5 * v + 3] + g_h2sq[5 * v + 4]) * invN * 0.2f;
        g_scale[t] = rsqrtf(ms + EPS);
        g_bias[t] = 0.f;
    }
}

// ---------------- normalize node output in place ----------------
__global__ void __launch_bounds__(128) k_norm(float* __restrict__ out) {
    int t = threadIdx.x;
    if (t >= 120) return;
    float4 sc = *(const float4*)(g_scale + 4 * t);
    float4 bs = *(const float4*)(g_bias + 4 * t);
    for (int n = blockIdx.x; n < NN; n += gridDim.x) {
        float4* p = (float4*)(out + (size_t)n * 480) + t;
        float4 v = *p;
        v.x = fmaf(v.x, sc.x, bs.x);
        v.y = fmaf(v.y, sc.y, bs.y);
        v.z = fmaf(v.z, sc.z, bs.z);
        v.w = fmaf(v.w, sc.w, bs.w);
        *p = v;
    }
}

// ---------------- launch ----------------
extern "C" void kernel_launch(void* const* d_in, const int* in_sizes, int n_in,
                              void* d_out, int out_size) {
    const float* x   = (const float*)d_in[0];
    const float* pos = (const float*)d_in[1];
    const int*   ei  = (const int*)d_in[2];
    const float* tpw = (const float*)d_in[3];
    const float* W0a = (const float*)d_in[4];
    const float* W1a = (const float*)d_in[5];
    const float* W2a = (const float*)d_in[6];
    const float* W0b = (const float*)d_in[7];
    const float* W1b = (const float*)d_in[8];
    const float* W2b = (const float*)d_in[9];

    float* out  = (float*)d_out;
    float* erbf = out + (size_t)NN * 480;
    float* ersh = erbf + (size_t)NE * 16;

    cudaFuncSetAttribute(k_node, cudaFuncAttributeMaxDynamicSharedMemorySize, SMEM_BYTES);

    k_zero<<<512, 256>>>();
    k_init<<<1, 32>>>();
    k_prep<<<(NN + 255) / 256, 256>>>(x, pos);
    k_edge<<<(NE + 255) / 256, 256>>>(ei, erbf, ersh);
    k_node<<<148, 256, SMEM_BYTES>>>(tpw, W0a, W1a, W2a, W0b, W1b, W2b, out);
    k_scale<<<1, 512>>>();
    k_norm<<<1184, 128>>>(out);
}

// round 3
// speedup vs baseline: 1.9567x; 1.5454x over previous
#include <cuda_runtime.h>
#include <math.h>
#include <stdint.h>

#define NN 100000
#define NE 3200000
#define NTILES 3125   // NN / 32

// ---------------- device scratch ----------------
__device__ float g_a[NN * 12];         // segment sums, padded stride 12
__device__ float g_xp[NN * 12];        // padded x
__device__ float4 g_pos4[NN];          // permuted pos
__device__ float g_C112[45];
__device__ float g_W222[125];
__device__ float g_h0sum[128];
__device__ float g_h0sq[128];
__device__ float g_h1sq[192];
__device__ float g_h2sq[160];
__device__ __align__(16) float g_scale[480];
__device__ __align__(16) float g_bias[480];

__device__ __forceinline__ float fsigmoid(float x) {
    return __fdividef(1.f, 1.f + __expf(-x));
}

// ---------------- zero scratch ----------------
__global__ void k_zero() {
    int i = blockIdx.x * blockDim.x + threadIdx.x;
    int stride = gridDim.x * blockDim.x;
    for (; i < NN * 12; i += stride) g_a[i] = 0.f;
    if (blockIdx.x == 0) {
        for (int j = threadIdx.x; j < 128; j += blockDim.x) { g_h0sum[j] = 0.f; g_h0sq[j] = 0.f; }
        for (int j = threadIdx.x; j < 192; j += blockDim.x) g_h1sq[j] = 0.f;
        for (int j = threadIdx.x; j < 160; j += blockDim.x) g_h2sq[j] = 0.f;
    }
}

// ---------------- constant tensors ----------------
__global__ void k_init() {
    if (threadIdx.x != 0 || blockIdx.x != 0) return;
    float A[5][3][3];
    for (int m = 0; m < 5; m++)
        for (int i = 0; i < 3; i++)
            for (int j = 0; j < 3; j++) A[m][i][j] = 0.f;
    const float h = sqrtf(15.f) * 0.5f;
    const float s5 = sqrtf(5.f);
    A[0][0][2] = h; A[0][2][0] = h;
    A[1][0][1] = h; A[1][1][0] = h;
    A[2][0][0] = -0.5f * s5; A[2][1][1] = s5; A[2][2][2] = -0.5f * s5;
    A[3][1][2] = h; A[3][2][1] = h;
    A[4][0][0] = -h; A[4][2][2] = h;
    float ss = 0.f;
    for (int m = 0; m < 5; m++)
        for (int i = 0; i < 3; i++)
            for (int j = 0; j < 3; j++) ss += A[m][i][j] * A[m][i][j];
    float inv = 1.f / sqrtf(ss);
    for (int i = 0; i < 3; i++)
        for (int j = 0; j < 3; j++)
            for (int m = 0; m < 5; m++)
                g_C112[i * 15 + j * 5 + m] = A[m][i][j] * inv;
    float Ws[5][5][5];
    float ss2 = 0.f;
    for (int m = 0; m < 5; m++)
        for (int n = 0; n < 5; n++)
            for (int p = 0; p < 5; p++) {
                float acc = 0.f, acc2 = 0.f;
                for (int i = 0; i < 3; i++)
                    for (int k = 0; k < 3; k++)
                        for (int j = 0; j < 3; j++) {
                            acc  += A[m][i][k] * A[n][k][j] * A[p][j][i];
                            acc2 += A[n][i][k] * A[m][k][j] * A[p][j][i];
                        }
                Ws[m][n][p] = acc + acc2;
                ss2 += (acc + acc2) * (acc + acc2);
            }
    float inv2 = 1.f / sqrtf(ss2);
    for (int m = 0; m < 5; m++)
        for (int n = 0; n < 5; n++)
            for (int p = 0; p < 5; p++)
                g_W222[(m * 5 + n) * 5 + p] = Ws[m][n][p] * inv2;
}

// ---------------- prep: pad x, permute pos ----------------
__global__ void k_prep(const float* __restrict__ x, const float* __restrict__ pos) {
    int n = blockIdx.x * blockDim.x + threadIdx.x;
    if (n >= NN) return;
    float4 p;
    p.x = pos[3 * n + 1]; p.y = pos[3 * n + 2]; p.z = pos[3 * n + 0]; p.w = 0.f;
    g_pos4[n] = p;
    const float* xs = x + 9 * (size_t)n;
    float4* xp = (float4*)(g_xp + 12 * (size_t)n);
    xp[0] = make_float4(xs[0], xs[1], xs[2], xs[3]);
    xp[1] = make_float4(xs[4], xs[5], xs[6], xs[7]);
    xp[2] = make_float4(xs[8], 0.f, 0.f, 0.f);
}

// ---------------- edge kernel (smem-staged coalesced outputs) ----------------
__global__ void __launch_bounds__(256) k_edge(
    const int* __restrict__ ei,
    float* __restrict__ erbf, float* __restrict__ ersh)
{
    __shared__ float s_rbf[256 * 16];
    __shared__ float s_sh9[256 * 9];
    const int tid = threadIdx.x;
    const int e0 = blockIdx.x * 256;
    const int e = e0 + tid;

    int s = ei[e];
    int t = ei[NE + e];
    float4 ps = g_pos4[s], pt = g_pos4[t];
    float vx = pt.x - ps.x, vy = pt.y - ps.y, vz = pt.z - ps.z;
    float r2 = vx * vx + vy * vy + vz * vz;
    float r = sqrtf(r2);
    float inv = __fdividef(1.f, fmaxf(r, 1e-12f));
    float ux = vx * inv, uy = vy * inv, uz = vz * inv;
    const float SQ3 = 1.7320508075688772f;
    const float SQ5 = 2.2360679774997896f;
    const float SQ15 = 3.8729833462074170f;
    float sh1 = SQ3 * ux, sh2 = SQ3 * uy, sh3 = SQ3 * uz;
    float sh4 = SQ15 * ux * uz;
    float sh5 = SQ15 * ux * uy;
    float sh6 = SQ5 * (uy * uy - 0.5f * (ux * ux + uz * uz));
    float sh7 = SQ15 * uy * uz;
    float sh8 = 0.5f * SQ15 * (uz * uz - ux * ux);
    float d = r * 0.1f;
    float d2 = d * d;
    float d5 = d2 * d2 * d;
    float fc = 1.f + d5 * (-21.f + d * (35.f - 15.f * d));
    fc = (d < 1.f) ? fc : 0.f;
    float ee = __expf(-d2) * fc;
    float g0 = ee, g1 = d * ee, g2 = d2 * ee;

    const float4* xp = (const float4*)(g_xp + 12 * (size_t)s);
    float4 xa = xp[0], xb = xp[1];
    float x8 = g_xp[12 * (size_t)s + 8];

    float* ga = g_a + 12 * (size_t)t;
    float m0 = xa.x * g0;
    float m1 = xa.y * sh1 * g1;
    float m2 = xa.z * sh2 * g1;
    float m3 = xa.w * sh3 * g1;
    float m4 = xb.x * sh4 * g2;
    float m5 = xb.y * sh5 * g2;
    float m6 = xb.z * sh6 * g2;
    float m7 = xb.w * sh7 * g2;
    float m8 = x8   * sh8 * g2;
    asm volatile("red.global.add.v4.f32 [%0], {%1,%2,%3,%4};"
                 :: "l"(ga), "f"(m0), "f"(m1), "f"(m2), "f"(m3) : "memory");
    asm volatile("red.global.add.v4.f32 [%0], {%1,%2,%3,%4};"
                 :: "l"(ga + 4), "f"(m4), "f"(m5), "f"(m6), "f"(m7) : "memory");
    atomicAdd(ga + 8, m8);

    // erbf via sin recurrence -> smem
    float sp, cp;
    __sincosf(0.31415926535897931f * r, &sp, &cp);
    float coef = 0.44721359549995793f * inv * fc;
    float* rb = s_rbf + tid * 16;
    float sprev = 0.f, scur = sp;
    float twoc = 2.f * cp;
#pragma unroll
    for (int n = 0; n < 16; n++) {
        rb[n] = coef * scur;
        float nx = twoc * scur - sprev;
        sprev = scur; scur = nx;
    }
    float* es = s_sh9 + tid * 9;
    es[0] = 1.f;
    es[1] = -sh1; es[2] = -sh2; es[3] = -sh3;
    es[4] = sh4; es[5] = sh5; es[6] = sh6; es[7] = sh7; es[8] = sh8;
    __syncthreads();

    // coalesced writeout
    float4* eb = (float4*)(erbf + (size_t)e0 * 16);
    const float4* sb = (const float4*)s_rbf;
#pragma unroll
    for (int i = 0; i < 4; i++) {
        int j = tid + 256 * i;
        eb[j] = sb[j];
    }
    float* ep = ersh + (size_t)e0 * 9;
#pragma unroll
    for (int i = 0; i < 9; i++) {
        int j = tid + 256 * i;
        ep[j] = s_sh9[j];
    }
}

// ---------------- node kernel: lane=node stage B ----------------
#define SM_W0A   0        // 384
#define SM_W1A   384      // 256
#define SM_W2A   640      // 128
#define SM_W0B   768      // 16384 [k][f]
#define SM_W1B   17152    // 4096  [u][v]
#define SM_W2B   21248    // 1024  [u][v]
#define SM_TPW   22272    // 12
#define SM_C112  22284    // 48
#define SM_W222  22332    // 128
#define SM_S     22460    // 32*13 = 416
#define SM_OUTT  22876    // 35*32 = 1120
#define SM_H0    23996    // 128*32 = 4096
#define SM_H1    28092    // 192*32 = 6144
#define SM_H2    34236    // 160*32 = 5120
#define SMEM_FLOATS 39356
#define SMEM_BYTES (SMEM_FLOATS * 4)

__global__ void __launch_bounds__(512) k_node(
    const float* __restrict__ tp_w,
    const float* __restrict__ W0a, const float* __restrict__ W1a, const float* __restrict__ W2a,
    const float* __restrict__ W0b, const float* __restrict__ W1b, const float* __restrict__ W2b,
    float* __restrict__ out)
{
    extern __shared__ float sm[];
    float* w0a  = sm + SM_W0A;
    float* w1a  = sm + SM_W1A;
    float* w2a  = sm + SM_W2A;
    float* w0b  = sm + SM_W0B;
    float* w1b  = sm + SM_W1B;
    float* w2b  = sm + SM_W2B;
    float* tpw  = sm + SM_TPW;
    float* c112 = sm + SM_C112;
    float* w222 = sm + SM_W222;
    float* s_sh = sm + SM_S;     // stride 13 per node
    float* out_t = sm + SM_OUTT; // [q][32]
    float* h0aT = sm + SM_H0;    // [k][32]
    float* h1aT = sm + SM_H1;    // [(u*3+m)][32]
    float* h2aT = sm + SM_H2;    // [(u*5+m)][32]

    const int tid = threadIdx.x;
    const int wid = tid >> 5;
    const int lane = tid & 31;

    for (int i = tid; i < 384; i += 512) w0a[i] = W0a[i];
    if (tid < 256) w1a[tid] = W1a[tid];
    if (tid >= 256 && tid < 384) w2a[tid - 256] = W2a[tid - 256];
    for (int i = tid; i < 16384; i += 512) w0b[i] = W0b[i];
    for (int i = tid; i < 4096;  i += 512) w1b[i] = W1b[i];
    for (int i = tid; i < 1024;  i += 512) w2b[i] = W2b[i];
    if (tid < 11)  tpw[tid]  = tp_w[tid];
    if (tid >= 32 && tid < 77)  c112[tid - 32] = g_C112[tid - 32];
    if (tid >= 128 && tid < 253) w222[tid - 128] = g_W222[tid - 128];
    __syncthreads();

    // per-lane running stats (static warp->task map across tiles)
    float sq[8][4];
    float sm0[2][4];
#pragma unroll
    for (int k = 0; k < 8; k++) { sq[k][0] = sq[k][1] = sq[k][2] = sq[k][3] = 0.f; }
    sm0[0][0] = sm0[0][1] = sm0[0][2] = sm0[0][3] = 0.f;
    sm0[1][0] = sm0[1][1] = sm0[1][2] = sm0[1][3] = 0.f;

    for (int tile = blockIdx.x; tile < NTILES; tile += gridDim.x) {
        const int n0 = tile * 32;

        // load s for 32 nodes
        if (tid < 96) {
            int n = tid / 3;
            int c = tid - 3 * n;
            const float4* gp = (const float4*)(g_a + (size_t)(n0 + n) * 12);
            float4 v = gp[c];
            float* dst = s_sh + n * 13 + c * 4;
            dst[0] = v.x; dst[1] = v.y; dst[2] = v.z; dst[3] = v.w;
        }
        __syncthreads();

        // tensor products -> out_t[q][n]
        for (int slot = tid; slot < 1120; slot += 512) {
            int q = slot >> 5, n = slot & 31;
            const float* s = s_sh + n * 13;
            float s0 = s[0];
            float val;
            if (q == 0) {
                val = tpw[0] * s0 * s0;
            } else if (q == 1) {
                float a = s[1] * s[1] + s[2] * s[2] + s[3] * s[3];
                val = tpw[1] * a * 0.57735026918962573f;
            } else if (q == 2) {
                float a = 0.f;
#pragma unroll
                for (int m = 0; m < 5; m++) a = fmaf(s[4 + m], s[4 + m], a);
                val = tpw[2] * a * 0.44721359549995793f;
            } else if (q < 6) {
                val = tpw[3] * s0 * s[1 + (q - 3)];
            } else if (q < 9) {
                val = tpw[4] * s[1 + (q - 6)] * s0;
            } else if (q < 12) {
                int j = q - 9; float a = 0.f;
#pragma unroll
                for (int i = 0; i < 3; i++)
#pragma unroll
                    for (int m = 0; m < 5; m++)
                        a = fmaf(c112[i * 15 + j * 5 + m], s[1 + i] * s[4 + m], a);
                val = tpw[5] * a;
            } else if (q < 15) {
                int i = q - 12; float a = 0.f;
#pragma unroll
                for (int j = 0; j < 3; j++)
#pragma unroll
                    for (int m = 0; m < 5; m++)
                        a = fmaf(c112[i * 15 + j * 5 + m], s[1 + j] * s[4 + m], a);
                val = tpw[6] * a;
            } else if (q < 20) {
                val = tpw[7] * s0 * s[4 + (q - 15)];
            } else if (q < 25) {
                val = tpw[8] * s[4 + (q - 20)] * s0;
            } else if (q < 30) {
                int m = q - 25; float a = 0.f;
#pragma unroll
                for (int i = 0; i < 3; i++)
#pragma unroll
                    for (int j = 0; j < 3; j++)
                        a = fmaf(c112[i * 15 + j * 5 + m], s[1 + i] * s[1 + j], a);
                val = tpw[9] * a;
            } else {
                int c = q - 30; float a = 0.f;
#pragma unroll
                for (int aa = 0; aa < 5; aa++)
#pragma unroll
                    for (int bb = 0; bb < 5; bb++)
                        a = fmaf(w222[(aa * 5 + bb) * 5 + c], s[4 + aa] * s[4 + bb], a);
                val = tpw[10] * a;
            }
            out_t[q * 32 + n] = val;
        }
        __syncthreads();

        // stage A
        for (int slot = tid; slot < 4096; slot += 512) {
            int f = slot >> 5, n = slot & 31;
            float hv = out_t[n] * w0a[f] + out_t[32 + n] * w0a[128 + f] + out_t[64 + n] * w0a[256 + f];
            h0aT[f * 32 + n] = fsigmoid(hv);
        }
        for (int slot = tid; slot < 2048; slot += 512) {
            int v = slot >> 5, n = slot & 31;
            float m0 = 0.f, m1 = 0.f, m2 = 0.f;
#pragma unroll
            for (int u = 0; u < 4; u++) {
                float w = w1a[u * 64 + v];
                m0 = fmaf(out_t[(3 + u * 3 + 0) * 32 + n], w, m0);
                m1 = fmaf(out_t[(3 + u * 3 + 1) * 32 + n], w, m1);
                m2 = fmaf(out_t[(3 + u * 3 + 2) * 32 + n], w, m2);
            }
            float gt = fsigmoid(sqrtf(m0 * m0 + m1 * m1 + m2 * m2));
            h1aT[(v * 3 + 0) * 32 + n] = m0 * gt;
            h1aT[(v * 3 + 1) * 32 + n] = m1 * gt;
            h1aT[(v * 3 + 2) * 32 + n] = m2 * gt;
        }
        for (int slot = tid; slot < 1024; slot += 512) {
            int v = slot >> 5, n = slot & 31;
            float m[5] = {0.f, 0.f, 0.f, 0.f, 0.f};
#pragma unroll
            for (int u = 0; u < 4; u++) {
                float w = w2a[u * 32 + v];
#pragma unroll
                for (int mm = 0; mm < 5; mm++)
                    m[mm] = fmaf(out_t[(15 + u * 5 + mm) * 32 + n], w, m[mm]);
            }
            float nrm = m[0]*m[0] + m[1]*m[1] + m[2]*m[2] + m[3]*m[3] + m[4]*m[4];
            float gt = fsigmoid(sqrtf(nrm));
#pragma unroll
            for (int mm = 0; mm < 5; mm++) h2aT[(v * 5 + mm) * 32 + n] = m[mm] * gt;
        }
        __syncthreads();

        // stage B: lane = node, warp task = 4 output features
        float* op_base = out + (size_t)(n0 + lane) * 480;
#pragma unroll
        for (int k8 = 0; k8 < 8; k8++) {
            const int t = wid + 16 * k8;
            if (t >= 120) continue;
            if (t < 32) {
                const float* ap = h0aT + lane;
                const float4* wp = (const float4*)(w0b + 4 * t);
                float a0 = 0.f, a1 = 0.f, a2 = 0.f, a3 = 0.f;
#pragma unroll 8
                for (int u = 0; u < 128; u++) {
                    float a = ap[u * 32];
                    float4 w = wp[u * 32];
                    a0 = fmaf(a, w.x, a0); a1 = fmaf(a, w.y, a1);
                    a2 = fmaf(a, w.z, a2); a3 = fmaf(a, w.w, a3);
                }
                *(float4*)(op_base + 4 * t) = make_float4(a0, a1, a2, a3);
                sm0[k8][0] += a0; sm0[k8][1] += a1; sm0[k8][2] += a2; sm0[k8][3] += a3;
                sq[k8][0] = fmaf(a0, a0, sq[k8][0]); sq[k8][1] = fmaf(a1, a1, sq[k8][1]);
                sq[k8][2] = fmaf(a2, a2, sq[k8][2]); sq[k8][3] = fmaf(a3, a3, sq[k8][3]);
            } else if (t < 80) {
                const int idx = t - 32, m = idx >> 4, vg = idx & 15;
                const float* ap = h1aT + m * 32 + lane;
                const float4* wp = (const float4*)(w1b + 4 * vg);
                float a0 = 0.f, a1 = 0.f, a2 = 0.f, a3 = 0.f;
#pragma unroll 8
                for (int u = 0; u < 64; u++) {
                    float a = ap[u * 96];
                    float4 w = wp[u * 16];
                    a0 = fmaf(a, w.x, a0); a1 = fmaf(a, w.y, a1);
                    a2 = fmaf(a, w.z, a2); a3 = fmaf(a, w.w, a3);
                }
                float* ob = op_base + 128 + m;
                ob[(4 * vg + 0) * 3] = a0; ob[(4 * vg + 1) * 3] = a1;
                ob[(4 * vg + 2) * 3] = a2; ob[(4 * vg + 3) * 3] = a3;
                sq[k8][0] = fmaf(a0, a0, sq[k8][0]); sq[k8][1] = fmaf(a1, a1, sq[k8][1]);
                sq[k8][2] = fmaf(a2, a2, sq[k8][2]); sq[k8][3] = fmaf(a3, a3, sq[k8][3]);
            } else {
                const int idx = t - 80, m = idx >> 3, vg = idx & 7;
                const float* ap = h2aT + m * 32 + lane;
                const float4* wp = (const float4*)(w2b + 4 * vg);
                float a0 = 0.f, a1 = 0.f, a2 = 0.f, a3 = 0.f;
#pragma unroll 8
                for (int u = 0; u < 32; u++) {
                    float a = ap[u * 160];
                    float4 w = wp[u * 8];
                    a0 = fmaf(a, w.x, a0); a1 = fmaf(a, w.y, a1);
                    a2 = fmaf(a, w.z, a2); a3 = fmaf(a, w.w, a3);
                }
                float* ob = op_base + 320 + m;
                ob[(4 * vg + 0) * 5] = a0; ob[(4 * vg + 1) * 5] = a1;
                ob[(4 * vg + 2) * 5] = a2; ob[(4 * vg + 3) * 5] = a3;
                sq[k8][0] = fmaf(a0, a0, sq[k8][0]); sq[k8][1] = fmaf(a1, a1, sq[k8][1]);
                sq[k8][2] = fmaf(a2, a2, sq[k8][2]); sq[k8][3] = fmaf(a3, a3, sq[k8][3]);
            }
        }
        __syncthreads();
    }

    // flush stats: warp-reduce per (task, feat)
#pragma unroll
    for (int k8 = 0; k8 < 8; k8++) {
        const int t = wid + 16 * k8;
        if (t >= 120) continue;
#pragma unroll
        for (int j = 0; j < 4; j++) {
            float v = sq[k8][j];
#pragma unroll
            for (int off = 16; off; off >>= 1) v += __shfl_xor_sync(0xffffffffu, v, off);
            if (lane == 0) {
                if (t < 32) atomicAdd(&g_h0sq[4 * t + j], v);
                else if (t < 80) { int idx = t - 32, m = idx >> 4, vg = idx & 15; atomicAdd(&g_h1sq[(4 * vg + j) * 3 + m], v); }
                else { int idx = t - 80, m = idx >> 3, vg = idx & 7; atomicAdd(&g_h2sq[(4 * vg + j) * 5 + m], v); }
            }
            if (t < 32) {
                float u2 = sm0[k8][j];
#pragma unroll
                for (int off = 16; off; off >>= 1) u2 += __shfl_xor_sync(0xffffffffu, u2, off);
                if (lane == 0) atomicAdd(&g_h0sum[4 * t + j], u2);
            }
        }
    }
}

// ---------------- scale/bias precompute ----------------
__global__ void k_scale() {
    int t = threadIdx.x;
    const float invN = 1.f / (float)NN;
    const float EPS = 1e-5f;
    if (t < 128) {
        float mean = g_h0sum[t] * invN;
        float var = g_h0sq[t] * invN - mean * mean;
        float sc = rsqrtf(var + EPS);
        g_scale[t] = sc;
        g_bias[t] = -mean * sc;
    } else if (t < 320) {
        int o = t - 128; int v = o / 3;
        float ms = (g_h1sq[3 * v] + g_h1sq[3 * v + 1] + g_h1sq[3 * v + 2]) * invN * (1.f / 3.f);
        g_scale[t] = rsqrtf(ms + EPS);
        g_bias[t] = 0.f;
    } else if (t < 480) {
        int o = t - 320; int v = o / 5;
        float ms = (g_h2sq[5 * v] + g_h2sq[5 * v + 1] + g_h2sq[5 * v + 2] +
                    g_h2sq[5 * v + 3] + g_h2sq[5 * v + 4]) * invN * 0.2f;
        g_scale[t] = rsqrtf(ms + EPS);
        g_bias[t] = 0.f;
    }
}

// ---------------- normalize node output in place ----------------
__global__ void __launch_bounds__(128) k_norm(float* __restrict__ out) {
    int t = threadIdx.x;
    if (t >= 120) return;
    float4 sc = *(const float4*)(g_scale + 4 * t);
    float4 bs = *(const float4*)(g_bias + 4 * t);
    for (int n = blockIdx.x; n < NN; n += gridDim.x) {
        float4* p = (float4*)(out + (size_t)n * 480) + t;
        float4 v = *p;
        v.x = fmaf(v.x, sc.x, bs.x);
        v.y = fmaf(v.y, sc.y, bs.y);
        v.z = fmaf(v.z, sc.z, bs.z);
        v.w = fmaf(v.w, sc.w, bs.w);
        *p = v;
    }
}

// ---------------- launch ----------------
extern "C" void kernel_launch(void* const* d_in, const int* in_sizes, int n_in,
                              void* d_out, int out_size) {
    const float* x   = (const float*)d_in[0];
    const float* pos = (const float*)d_in[1];
    const int*   ei  = (const int*)d_in[2];
    const float* tpw = (const float*)d_in[3];
    const float* W0a = (const float*)d_in[4];
    const float* W1a = (const float*)d_in[5];
    const float* W2a = (const float*)d_in[6];
    const float* W0b = (const float*)d_in[7];
    const float* W1b = (const float*)d_in[8];
    const float* W2b = (const float*)d_in[9];

    float* out  = (float*)d_out;
    float* erbf = out + (size_t)NN * 480;
    float* ersh = erbf + (size_t)NE * 16;

    cudaFuncSetAttribute(k_node, cudaFuncAttributeMaxDynamicSharedMemorySize, SMEM_BYTES);

    k_zero<<<512, 256>>>();
    k_init<<<1, 32>>>();
    k_prep<<<(NN + 255) / 256, 256>>>(x, pos);
    k_edge<<<NE / 256, 256>>>(ei, erbf, ersh);
    k_node<<<148, 512, SMEM_BYTES>>>(tpw, W0a, W1a, W2a, W0b, W1b, W2b, out);
    k_scale<<<1, 512>>>();
    k_norm<<<1184, 128>>>(out);
}

// round 4
// speedup vs baseline: 2.6820x; 1.3706x over previous
#include <cuda_runtime.h>
#include <math.h>
#include <stdint.h>

#define NN 100000
#define NE 3200000
#define NTILES 3125   // NN / 32

typedef unsigned long long ull;

// ---------------- device scratch ----------------
__device__ float g_a[NN * 12];         // segment sums, padded stride 12
__device__ float g_xp[NN * 12];        // padded x
__device__ float4 g_pos4[NN];          // permuted pos
__device__ float g_C112[45];
__device__ float g_W222[125];
__device__ float g_h0sum[128];
__device__ float g_h0sq[128];
__device__ float g_h1sq[192];
__device__ float g_h2sq[160];
__device__ __align__(16) float g_scale[480];
__device__ __align__(16) float g_bias[480];

__device__ __forceinline__ float fsigmoid(float x) {
    return __fdividef(1.f, 1.f + __expf(-x));
}
__device__ __forceinline__ ull pack2(float a, float b) {
    ull r; asm("mov.b64 %0, {%1,%2};" : "=l"(r) : "f"(a), "f"(b)); return r;
}
__device__ __forceinline__ void fma2(ull& d, ull a, ull b) {
    asm("fma.rn.f32x2 %0, %1, %2, %0;" : "+l"(d) : "l"(a), "l"(b));
}
__device__ __forceinline__ void unpack2(ull v, float& a, float& b) {
    asm("mov.b64 {%0,%1}, %2;" : "=f"(a), "=f"(b) : "l"(v));
}

// ---------------- zero scratch ----------------
__global__ void k_zero() {
    int i = blockIdx.x * blockDim.x + threadIdx.x;
    int stride = gridDim.x * blockDim.x;
    for (; i < NN * 12; i += stride) g_a[i] = 0.f;
    if (blockIdx.x == 0) {
        for (int j = threadIdx.x; j < 128; j += blockDim.x) { g_h0sum[j] = 0.f; g_h0sq[j] = 0.f; }
        for (int j = threadIdx.x; j < 192; j += blockDim.x) g_h1sq[j] = 0.f;
        for (int j = threadIdx.x; j < 160; j += blockDim.x) g_h2sq[j] = 0.f;
    }
}

// ---------------- constant tensors ----------------
__global__ void k_init() {
    if (threadIdx.x != 0 || blockIdx.x != 0) return;
    float A[5][3][3];
    for (int m = 0; m < 5; m++)
        for (int i = 0; i < 3; i++)
            for (int j = 0; j < 3; j++) A[m][i][j] = 0.f;
    const float h = sqrtf(15.f) * 0.5f;
    const float s5 = sqrtf(5.f);
    A[0][0][2] = h; A[0][2][0] = h;
    A[1][0][1] = h; A[1][1][0] = h;
    A[2][0][0] = -0.5f * s5; A[2][1][1] = s5; A[2][2][2] = -0.5f * s5;
    A[3][1][2] = h; A[3][2][1] = h;
    A[4][0][0] = -h; A[4][2][2] = h;
    float ss = 0.f;
    for (int m = 0; m < 5; m++)
        for (int i = 0; i < 3; i++)
            for (int j = 0; j < 3; j++) ss += A[m][i][j] * A[m][i][j];
    float inv = 1.f / sqrtf(ss);
    for (int i = 0; i < 3; i++)
        for (int j = 0; j < 3; j++)
            for (int m = 0; m < 5; m++)
                g_C112[i * 15 + j * 5 + m] = A[m][i][j] * inv;
    float Ws[5][5][5];
    float ss2 = 0.f;
    for (int m = 0; m < 5; m++)
        for (int n = 0; n < 5; n++)
            for (int p = 0; p < 5; p++) {
                float acc = 0.f, acc2 = 0.f;
                for (int i = 0; i < 3; i++)
                    for (int k = 0; k < 3; k++)
                        for (int j = 0; j < 3; j++) {
                            acc  += A[m][i][k] * A[n][k][j] * A[p][j][i];
                            acc2 += A[n][i][k] * A[m][k][j] * A[p][j][i];
                        }
                Ws[m][n][p] = acc + acc2;
                ss2 += (acc + acc2) * (acc + acc2);
            }
    float inv2 = 1.f / sqrtf(ss2);
    for (int m = 0; m < 5; m++)
        for (int n = 0; n < 5; n++)
            for (int p = 0; p < 5; p++)
                g_W222[(m * 5 + n) * 5 + p] = Ws[m][n][p] * inv2;
}

// ---------------- prep: pad x, permute pos ----------------
__global__ void k_prep(const float* __restrict__ x, const float* __restrict__ pos) {
    int n = blockIdx.x * blockDim.x + threadIdx.x;
    if (n >= NN) return;
    float4 p;
    p.x = pos[3 * n + 1]; p.y = pos[3 * n + 2]; p.z = pos[3 * n + 0]; p.w = 0.f;
    g_pos4[n] = p;
    const float* xs = x + 9 * (size_t)n;
    float4* xp = (float4*)(g_xp + 12 * (size_t)n);
    xp[0] = make_float4(xs[0], xs[1], xs[2], xs[3]);
    xp[1] = make_float4(xs[4], xs[5], xs[6], xs[7]);
    xp[2] = make_float4(xs[8], 0.f, 0.f, 0.f);
}

// ---------------- edge kernel ----------------
__global__ void __launch_bounds__(256) k_edge(
    const int* __restrict__ ei,
    float* __restrict__ erbf, float* __restrict__ ersh)
{
    __shared__ float s_rbf[256 * 17];   // stride 17: conflict-free
    __shared__ float s_sh9[256 * 9];
    const int tid = threadIdx.x;
    const int e0 = blockIdx.x * 256;
    const int e = e0 + tid;

    int s = ei[e];
    int t = ei[NE + e];
    float4 ps = g_pos4[s], pt = g_pos4[t];
    float vx = pt.x - ps.x, vy = pt.y - ps.y, vz = pt.z - ps.z;
    float r2 = vx * vx + vy * vy + vz * vz;
    float r = sqrtf(r2);
    float inv = __fdividef(1.f, fmaxf(r, 1e-12f));
    float ux = vx * inv, uy = vy * inv, uz = vz * inv;
    const float SQ3 = 1.7320508075688772f;
    const float SQ5 = 2.2360679774997896f;
    const float SQ15 = 3.8729833462074170f;
    float sh1 = SQ3 * ux, sh2 = SQ3 * uy, sh3 = SQ3 * uz;
    float sh4 = SQ15 * ux * uz;
    float sh5 = SQ15 * ux * uy;
    float sh6 = SQ5 * (uy * uy - 0.5f * (ux * ux + uz * uz));
    float sh7 = SQ15 * uy * uz;
    float sh8 = 0.5f * SQ15 * (uz * uz - ux * ux);
    float d = r * 0.1f;
    float d2 = d * d;
    float d5 = d2 * d2 * d;
    float fc = 1.f + d5 * (-21.f + d * (35.f - 15.f * d));
    fc = (d < 1.f) ? fc : 0.f;
    float ee = __expf(-d2) * fc;
    float g0 = ee, g1 = d * ee, g2 = d2 * ee;

    const float4* xp = (const float4*)(g_xp + 12 * (size_t)s);
    float4 xa = xp[0], xb = xp[1];
    float x8 = g_xp[12 * (size_t)s + 8];

    float* ga = g_a + 12 * (size_t)t;
    float m0 = xa.x * g0;
    float m1 = xa.y * sh1 * g1;
    float m2 = xa.z * sh2 * g1;
    float m3 = xa.w * sh3 * g1;
    float m4 = xb.x * sh4 * g2;
    float m5 = xb.y * sh5 * g2;
    float m6 = xb.z * sh6 * g2;
    float m7 = xb.w * sh7 * g2;
    float m8 = x8   * sh8 * g2;
    asm volatile("red.global.add.v4.f32 [%0], {%1,%2,%3,%4};"
                 :: "l"(ga), "f"(m0), "f"(m1), "f"(m2), "f"(m3) : "memory");
    asm volatile("red.global.add.v4.f32 [%0], {%1,%2,%3,%4};"
                 :: "l"(ga + 4), "f"(m4), "f"(m5), "f"(m6), "f"(m7) : "memory");
    atomicAdd(ga + 8, m8);

    // erbf via sin recurrence -> smem (stride 17)
    float sp, cp;
    __sincosf(0.31415926535897931f * r, &sp, &cp);
    float coef = 0.44721359549995793f * inv * fc;
    float* rb = s_rbf + tid * 17;
    float sprev = 0.f, scur = sp;
    float twoc = 2.f * cp;
#pragma unroll
    for (int n = 0; n < 16; n++) {
        rb[n] = coef * scur;
        float nx = twoc * scur - sprev;
        sprev = scur; scur = nx;
    }
    float* es = s_sh9 + tid * 9;
    es[0] = 1.f;
    es[1] = -sh1; es[2] = -sh2; es[3] = -sh3;
    es[4] = sh4; es[5] = sh5; es[6] = sh6; es[7] = sh7; es[8] = sh8;
    __syncthreads();

    // coalesced scalar writeout
    float* eb = erbf + (size_t)e0 * 16;
#pragma unroll
    for (int i = 0; i < 16; i++) {
        int j = tid + 256 * i;
        eb[j] = s_rbf[(j >> 4) * 17 + (j & 15)];
    }
    float* ep = ersh + (size_t)e0 * 9;
#pragma unroll
    for (int i = 0; i < 9; i++) {
        int j = tid + 256 * i;
        ep[j] = s_sh9[j];
    }
}

// ---------------- node kernel ----------------
#define SM_W0A   0        // 384
#define SM_W1A   384      // 256
#define SM_W2A   640      // 128
#define SM_W0B   768      // 16384 [k][f]
#define SM_W1B   17152    // 4096  [u][v]
#define SM_W2B   21248    // 1024  [u][v]
#define SM_TPW   22272    // 12
#define SM_C112  22284    // 48
#define SM_W222  22332    // 128
#define SM_S     22460    // 32*13 = 416
#define SM_OUTT  22876    // 35*32 = 1120
#define SM_H0    23996    // 128*32 = 4096
#define SM_H1    28092    // 192*32 = 6144
#define SM_H2    34236    // 160*32 = 5120
#define SM_OUT   39360    // 480*33 = 15840 (16B aligned base)
#define SMEM_FLOATS 55200
#define SMEM_BYTES (SMEM_FLOATS * 4)

__global__ void __launch_bounds__(512) k_node(
    const float* __restrict__ tp_w,
    const float* __restrict__ W0a, const float* __restrict__ W1a, const float* __restrict__ W2a,
    const float* __restrict__ W0b, const float* __restrict__ W1b, const float* __restrict__ W2b,
    float* __restrict__ out)
{
    extern __shared__ float sm[];
    float* w0a  = sm + SM_W0A;
    float* w1a  = sm + SM_W1A;
    float* w2a  = sm + SM_W2A;
    float* w0b  = sm + SM_W0B;
    float* w1b  = sm + SM_W1B;
    float* w2b  = sm + SM_W2B;
    float* tpw  = sm + SM_TPW;
    float* c112 = sm + SM_C112;
    float* w222 = sm + SM_W222;
    float* s_sh = sm + SM_S;     // stride 13 per node
    float* out_t = sm + SM_OUTT; // [q][32]
    float* h0aT = sm + SM_H0;    // [k][32]
    float* h1aT = sm + SM_H1;    // [(u*3+m)][32]
    float* h2aT = sm + SM_H2;    // [(u*5+m)][32]
    float* s_out = sm + SM_OUT;  // [f][33]

    const int tid = threadIdx.x;
    const int wid = tid >> 5;
    const int lane = tid & 31;

    for (int i = tid; i < 384; i += 512) w0a[i] = W0a[i];
    if (tid < 256) w1a[tid] = W1a[tid];
    if (tid >= 256 && tid < 384) w2a[tid - 256] = W2a[tid - 256];
    for (int i = tid; i < 16384; i += 512) w0b[i] = W0b[i];
    for (int i = tid; i < 4096;  i += 512) w1b[i] = W1b[i];
    for (int i = tid; i < 1024;  i += 512) w2b[i] = W2b[i];
    if (tid < 11)  tpw[tid]  = tp_w[tid];
    if (tid >= 32 && tid < 77)  c112[tid - 32] = g_C112[tid - 32];
    if (tid >= 128 && tid < 253) w222[tid - 128] = g_W222[tid - 128];
    __syncthreads();

    // per-lane running stats: 4 rounds (k8) x 8 feats
    float sq[4][8];
    float sm0[8];
#pragma unroll
    for (int k = 0; k < 4; k++)
#pragma unroll
        for (int j = 0; j < 8; j++) sq[k][j] = 0.f;
#pragma unroll
    for (int j = 0; j < 8; j++) sm0[j] = 0.f;

    for (int tile = blockIdx.x; tile < NTILES; tile += gridDim.x) {
        const int n0 = tile * 32;

        if (tid < 96) {
            int n = tid / 3;
            int c = tid - 3 * n;
            const float4* gp = (const float4*)(g_a + (size_t)(n0 + n) * 12);
            float4 v = gp[c];
            float* dst = s_sh + n * 13 + c * 4;
            dst[0] = v.x; dst[1] = v.y; dst[2] = v.z; dst[3] = v.w;
        }
        __syncthreads();

        // tensor products -> out_t[q][n]
        for (int slot = tid; slot < 1120; slot += 512) {
            int q = slot >> 5, n = slot & 31;
            const float* s = s_sh + n * 13;
            float s0 = s[0];
            float val;
            if (q == 0) {
                val = tpw[0] * s0 * s0;
            } else if (q == 1) {
                float a = s[1] * s[1] + s[2] * s[2] + s[3] * s[3];
                val = tpw[1] * a * 0.57735026918962573f;
            } else if (q == 2) {
                float a = 0.f;
#pragma unroll
                for (int m = 0; m < 5; m++) a = fmaf(s[4 + m], s[4 + m], a);
                val = tpw[2] * a * 0.44721359549995793f;
            } else if (q < 6) {
                val = tpw[3] * s0 * s[1 + (q - 3)];
            } else if (q < 9) {
                val = tpw[4] * s[1 + (q - 6)] * s0;
            } else if (q < 12) {
                int j = q - 9; float a = 0.f;
#pragma unroll
                for (int i = 0; i < 3; i++)
#pragma unroll
                    for (int m = 0; m < 5; m++)
                        a = fmaf(c112[i * 15 + j * 5 + m], s[1 + i] * s[4 + m], a);
                val = tpw[5] * a;
            } else if (q < 15) {
                int i = q - 12; float a = 0.f;
#pragma unroll
                for (int j = 0; j < 3; j++)
#pragma unroll
                    for (int m = 0; m < 5; m++)
                        a = fmaf(c112[i * 15 + j * 5 + m], s[1 + j] * s[4 + m], a);
                val = tpw[6] * a;
            } else if (q < 20) {
                val = tpw[7] * s0 * s[4 + (q - 15)];
            } else if (q < 25) {
                val = tpw[8] * s[4 + (q - 20)] * s0;
            } else if (q < 30) {
                int m = q - 25; float a = 0.f;
#pragma unroll
                for (int i = 0; i < 3; i++)
#pragma unroll
                    for (int j = 0; j < 3; j++)
                        a = fmaf(c112[i * 15 + j * 5 + m], s[1 + i] * s[1 + j], a);
                val = tpw[9] * a;
            } else {
                int c = q - 30; float a = 0.f;
#pragma unroll
                for (int aa = 0; aa < 5; aa++)
#pragma unroll
                    for (int bb = 0; bb < 5; bb++)
                        a = fmaf(w222[(aa * 5 + bb) * 5 + c], s[4 + aa] * s[4 + bb], a);
                val = tpw[10] * a;
            }
            out_t[q * 32 + n] = val;
        }
        __syncthreads();

        // stage A
        for (int slot = tid; slot < 4096; slot += 512) {
            int f = slot >> 5, n = slot & 31;
            float hv = out_t[n] * w0a[f] + out_t[32 + n] * w0a[128 + f] + out_t[64 + n] * w0a[256 + f];
            h0aT[f * 32 + n] = fsigmoid(hv);
        }
        for (int slot = tid; slot < 2048; slot += 512) {
            int v = slot >> 5, n = slot & 31;
            float m0 = 0.f, m1 = 0.f, m2 = 0.f;
#pragma unroll
            for (int u = 0; u < 4; u++) {
                float w = w1a[u * 64 + v];
                m0 = fmaf(out_t[(3 + u * 3 + 0) * 32 + n], w, m0);
                m1 = fmaf(out_t[(3 + u * 3 + 1) * 32 + n], w, m1);
                m2 = fmaf(out_t[(3 + u * 3 + 2) * 32 + n], w, m2);
            }
            float gt = fsigmoid(sqrtf(m0 * m0 + m1 * m1 + m2 * m2));
            h1aT[(v * 3 + 0) * 32 + n] = m0 * gt;
            h1aT[(v * 3 + 1) * 32 + n] = m1 * gt;
            h1aT[(v * 3 + 2) * 32 + n] = m2 * gt;
        }
        for (int slot = tid; slot < 1024; slot += 512) {
            int v = slot >> 5, n = slot & 31;
            float m[5] = {0.f, 0.f, 0.f, 0.f, 0.f};
#pragma unroll
            for (int u = 0; u < 4; u++) {
                float w = w2a[u * 32 + v];
#pragma unroll
                for (int mm = 0; mm < 5; mm++)
                    m[mm] = fmaf(out_t[(15 + u * 5 + mm) * 32 + n], w, m[mm]);
            }
            float nrm = m[0]*m[0] + m[1]*m[1] + m[2]*m[2] + m[3]*m[3] + m[4]*m[4];
            float gt = fsigmoid(sqrtf(nrm));
#pragma unroll
            for (int mm = 0; mm < 5; mm++) h2aT[(v * 5 + mm) * 32 + n] = m[mm] * gt;
        }
        __syncthreads();

        // stage B: warp task = 8 output features, lane = node; results -> s_out[f][33]
#pragma unroll
        for (int k8 = 0; k8 < 4; k8++) {
            const int t = wid + 16 * k8;
            if (t >= 60) continue;
            ull A0 = 0, A1 = 0, A2 = 0, A3 = 0;
            if (t < 16) {
                const float* ap = h0aT + lane;
                const ulonglong2* wp = (const ulonglong2*)(w0b + 8 * t);
#pragma unroll 4
                for (int u = 0; u < 128; u++) {
                    float a = ap[u * 32];
                    ull a2 = pack2(a, a);
                    ulonglong2 w01 = wp[u * 32];
                    ulonglong2 w23 = wp[u * 32 + 1];
                    fma2(A0, a2, w01.x); fma2(A1, a2, w01.y);
                    fma2(A2, a2, w23.x); fma2(A3, a2, w23.y);
                }
                float f[8];
                unpack2(A0, f[0], f[1]); unpack2(A1, f[2], f[3]);
                unpack2(A2, f[4], f[5]); unpack2(A3, f[6], f[7]);
#pragma unroll
                for (int j = 0; j < 8; j++) {
                    s_out[(8 * t + j) * 33 + lane] = f[j];
                    sm0[j] += f[j];
                    sq[k8][j] = fmaf(f[j], f[j], sq[k8][j]);
                }
            } else if (t < 40) {
                const int idx = t - 16, m = idx >> 3, vg = idx & 7;
                const float* ap = h1aT + m * 32 + lane;
                const ulonglong2* wp = (const ulonglong2*)(w1b + 8 * vg);
#pragma unroll 4
                for (int u = 0; u < 64; u++) {
                    float a = ap[u * 96];
                    ull a2 = pack2(a, a);
                    ulonglong2 w01 = wp[u * 16];
                    ulonglong2 w23 = wp[u * 16 + 1];
                    fma2(A0, a2, w01.x); fma2(A1, a2, w01.y);
                    fma2(A2, a2, w23.x); fma2(A3, a2, w23.y);
                }
                float f[8];
                unpack2(A0, f[0], f[1]); unpack2(A1, f[2], f[3]);
                unpack2(A2, f[4], f[5]); unpack2(A3, f[6], f[7]);
#pragma unroll
                for (int j = 0; j < 8; j++) {
                    s_out[(128 + (8 * vg + j) * 3 + m) * 33 + lane] = f[j];
                    sq[k8][j] = fmaf(f[j], f[j], sq[k8][j]);
                }
            } else {
                const int idx = t - 40, m = idx >> 2, vg = idx & 3;
                const float* ap = h2aT + m * 32 + lane;
                const ulonglong2* wp = (const ulonglong2*)(w2b + 8 * vg);
#pragma unroll 4
                for (int u = 0; u < 32; u++) {
                    float a = ap[u * 160];
                    ull a2 = pack2(a, a);
                    ulonglong2 w01 = wp[u * 8];
                    ulonglong2 w23 = wp[u * 8 + 1];
                    fma2(A0, a2, w01.x); fma2(A1, a2, w01.y);
                    fma2(A2, a2, w23.x); fma2(A3, a2, w23.y);
                }
                float f[8];
                unpack2(A0, f[0], f[1]); unpack2(A1, f[2], f[3]);
                unpack2(A2, f[4], f[5]); unpack2(A3, f[6], f[7]);
#pragma unroll
                for (int j = 0; j < 8; j++) {
                    s_out[(320 + (8 * vg + j) * 5 + m) * 33 + lane] = f[j];
                    sq[k8][j] = fmaf(f[j], f[j], sq[k8][j]);
                }
            }
        }
        __syncthreads();

        // coalesced writeback
        if (tid < 480) {
            float* ob = out + (size_t)n0 * 480 + tid;
#pragma unroll 8
            for (int n = 0; n < 32; n++)
                ob[(size_t)n * 480] = s_out[tid * 33 + n];
        }
        __syncthreads();
    }

    // flush stats
#pragma unroll
    for (int k8 = 0; k8 < 4; k8++) {
        const int t = wid + 16 * k8;
        if (t >= 60) continue;
#pragma unroll
        for (int j = 0; j < 8; j++) {
            float v = sq[k8][j];
#pragma unroll
            for (int off = 16; off; off >>= 1) v += __shfl_xor_sync(0xffffffffu, v, off);
            if (lane == 0) {
                if (t < 16) atomicAdd(&g_h0sq[8 * t + j], v);
                else if (t < 40) { int idx = t - 16, m = idx >> 3, vg = idx & 7; atomicAdd(&g_h1sq[(8 * vg + j) * 3 + m], v); }
                else { int idx = t - 40, m = idx >> 2, vg = idx & 3; atomicAdd(&g_h2sq[(8 * vg + j) * 5 + m], v); }
            }
            if (t < 16) {
                float u2 = sm0[j];
#pragma unroll
                for (int off = 16; off; off >>= 1) u2 += __shfl_xor_sync(0xffffffffu, u2, off);
                if (lane == 0) atomicAdd(&g_h0sum[8 * t + j], u2);
            }
        }
    }
}

// ---------------- scale/bias precompute ----------------
__global__ void k_scale() {
    int t = threadIdx.x;
    const float invN = 1.f / (float)NN;
    const float EPS = 1e-5f;
    if (t < 128) {
        float mean = g_h0sum[t] * invN;
        float var = g_h0sq[t] * invN - mean * mean;
        float sc = rsqrtf(var + EPS);
        g_scale[t] = sc;
        g_bias[t] = -mean * sc;
    } else if (t < 320) {
        int o = t - 128; int v = o / 3;
        float ms = (g_h1sq[3 * v] + g_h1sq[3 * v + 1] + g_h1sq[3 * v + 2]) * invN * (1.f / 3.f);
        g_scale[t] = rsqrtf(ms + EPS);
        g_bias[t] = 0.f;
    } else if (t < 480) {
        int o = t - 320; int v = o / 5;
        float ms = (g_h2sq[5 * v] + g_h2sq[5 * v + 1] + g_h2sq[5 * v + 2] +
                    g_h2sq[5 * v + 3] + g_h2sq[5 * v + 4]) * invN * 0.2f;
        g_scale[t] = rsqrtf(ms + EPS);
        g_bias[t] = 0.f;
    }
}

// ---------------- normalize node output in place ----------------
__global__ void __launch_bounds__(128) k_norm(float* __restrict__ out) {
    int t = threadIdx.x;
    if (t >= 120) return;
    float4 sc = *(const float4*)(g_scale + 4 * t);
    float4 bs = *(const float4*)(g_bias + 4 * t);
    for (int n = blockIdx.x; n < NN; n += gridDim.x) {
        float4* p = (float4*)(out + (size_t)n * 480) + t;
        float4 v = *p;
        v.x = fmaf(v.x, sc.x, bs.x);
        v.y = fmaf(v.y, sc.y, bs.y);
        v.z = fmaf(v.z, sc.z, bs.z);
        v.w = fmaf(v.w, sc.w, bs.w);
        *p = v;
    }
}

// ---------------- launch ----------------
extern "C" void kernel_launch(void* const* d_in, const int* in_sizes, int n_in,
                              void* d_out, int out_size) {
    const float* x   = (const float*)d_in[0];
    const float* pos = (const float*)d_in[1];
    const int*   ei  = (const int*)d_in[2];
    const float* tpw = (const float*)d_in[3];
    const float* W0a = (const float*)d_in[4];
    const float* W1a = (const float*)d_in[5];
    const float* W2a = (const float*)d_in[6];
    const float* W0b = (const float*)d_in[7];
    const float* W1b = (const float*)d_in[8];
    const float* W2b = (const float*)d_in[9];

    float* out  = (float*)d_out;
    float* erbf = out + (size_t)NN * 480;
    float* ersh = erbf + (size_t)NE * 16;

    cudaFuncSetAttribute(k_node, cudaFuncAttributeMaxDynamicSharedMemorySize, SMEM_BYTES);

    k_zero<<<512, 256>>>();
    k_init<<<1, 32>>>();
    k_prep<<<(NN + 255) / 256, 256>>>(x, pos);
    k_edge<<<NE / 256, 256>>>(ei, erbf, ersh);
    k_node<<<148, 512, SMEM_BYTES>>>(tpw, W0a, W1a, W2a, W0b, W1b, W2b, out);
    k_scale<<<1, 512>>>();
    k_norm<<<1184, 128>>>(out);
}

// round 5
// speedup vs baseline: 2.7511x; 1.0258x over previous
#include <cuda_runtime.h>
#include <math.h>
#include <stdint.h>

#define NN 100000
#define NE 3200000
#define NTILES 3125   // NN / 32

typedef unsigned long long ull;

// ---------------- device scratch ----------------
__device__ float g_a[NN * 12];         // segment sums, padded stride 12
__device__ float g_xp[NN * 12];        // padded x
__device__ float4 g_pos4[NN];          // permuted pos
__device__ float g_C112[45];
__device__ float g_W222[125];
__device__ float g_h0sum[128];
__device__ float g_h0sq[128];
__device__ float g_h1sq[192];
__device__ float g_h2sq[160];
__device__ __align__(16) float g_scale[480];
__device__ __align__(16) float g_bias[480];

__device__ __forceinline__ float fsigmoid(float x) {
    return __fdividef(1.f, 1.f + __expf(-x));
}
__device__ __forceinline__ ull pack2(float a, float b) {
    ull r; asm("mov.b64 %0, {%1,%2};" : "=l"(r) : "f"(a), "f"(b)); return r;
}
__device__ __forceinline__ void fma2(ull& d, ull a, ull b) {
    asm("fma.rn.f32x2 %0, %1, %2, %0;" : "+l"(d) : "l"(a), "l"(b));
}
__device__ __forceinline__ void unpack2(ull v, float& a, float& b) {
    asm("mov.b64 {%0,%1}, %2;" : "=f"(a), "=f"(b) : "l"(v));
}

// ---------------- constant tensors ----------------
__global__ void k_init() {
    if (threadIdx.x != 0 || blockIdx.x != 0) return;
    float A[5][3][3];
    for (int m = 0; m < 5; m++)
        for (int i = 0; i < 3; i++)
            for (int j = 0; j < 3; j++) A[m][i][j] = 0.f;
    const float h = sqrtf(15.f) * 0.5f;
    const float s5 = sqrtf(5.f);
    A[0][0][2] = h; A[0][2][0] = h;
    A[1][0][1] = h; A[1][1][0] = h;
    A[2][0][0] = -0.5f * s5; A[2][1][1] = s5; A[2][2][2] = -0.5f * s5;
    A[3][1][2] = h; A[3][2][1] = h;
    A[4][0][0] = -h; A[4][2][2] = h;
    float ss = 0.f;
    for (int m = 0; m < 5; m++)
        for (int i = 0; i < 3; i++)
            for (int j = 0; j < 3; j++) ss += A[m][i][j] * A[m][i][j];
    float inv = 1.f / sqrtf(ss);
    for (int i = 0; i < 3; i++)
        for (int j = 0; j < 3; j++)
            for (int m = 0; m < 5; m++)
                g_C112[i * 15 + j * 5 + m] = A[m][i][j] * inv;
    float Ws[5][5][5];
    float ss2 = 0.f;
    for (int m = 0; m < 5; m++)
        for (int n = 0; n < 5; n++)
            for (int p = 0; p < 5; p++) {
                float acc = 0.f, acc2 = 0.f;
                for (int i = 0; i < 3; i++)
                    for (int k = 0; k < 3; k++)
                        for (int j = 0; j < 3; j++) {
                            acc  += A[m][i][k] * A[n][k][j] * A[p][j][i];
                            acc2 += A[n][i][k] * A[m][k][j] * A[p][j][i];
                        }
                Ws[m][n][p] = acc + acc2;
                ss2 += (acc + acc2) * (acc + acc2);
            }
    float inv2 = 1.f / sqrtf(ss2);
    for (int m = 0; m < 5; m++)
        for (int n = 0; n < 5; n++)
            for (int p = 0; p < 5; p++)
                g_W222[(m * 5 + n) * 5 + p] = Ws[m][n][p] * inv2;
}

// ---------------- prep: pad x, permute pos, zero scratch ----------------
__global__ void k_prep(const float* __restrict__ x, const float* __restrict__ pos) {
    int n = blockIdx.x * blockDim.x + threadIdx.x;
    if (n < NN) {
        float4 p;
        p.x = pos[3 * n + 1]; p.y = pos[3 * n + 2]; p.z = pos[3 * n + 0]; p.w = 0.f;
        g_pos4[n] = p;
        const float* xs = x + 9 * (size_t)n;
        float4* xp = (float4*)(g_xp + 12 * (size_t)n);
        xp[0] = make_float4(xs[0], xs[1], xs[2], xs[3]);
        xp[1] = make_float4(xs[4], xs[5], xs[6], xs[7]);
        xp[2] = make_float4(xs[8], 0.f, 0.f, 0.f);
        float4 z = make_float4(0.f, 0.f, 0.f, 0.f);
        float4* ga = (float4*)(g_a + 12 * (size_t)n);
        ga[0] = z; ga[1] = z; ga[2] = z;
    }
    if (n < 128) { g_h0sum[n] = 0.f; g_h0sq[n] = 0.f; }
    if (n < 192) g_h1sq[n] = 0.f;
    if (n < 160) g_h2sq[n] = 0.f;
}

// ---------------- edge kernel ----------------
__global__ void __launch_bounds__(256) k_edge(
    const int* __restrict__ ei,
    float* __restrict__ erbf, float* __restrict__ ersh)
{
    __shared__ float s_rbf[256 * 17];   // stride 17: conflict-free
    __shared__ float s_sh9[256 * 9];
    const int tid = threadIdx.x;
    const int e0 = blockIdx.x * 256;
    const int e = e0 + tid;

    int s = ei[e];
    int t = ei[NE + e];
    float4 ps = g_pos4[s], pt = g_pos4[t];
    float vx = pt.x - ps.x, vy = pt.y - ps.y, vz = pt.z - ps.z;
    float r2 = vx * vx + vy * vy + vz * vz;
    float r = sqrtf(r2);
    float inv = __fdividef(1.f, fmaxf(r, 1e-12f));
    float ux = vx * inv, uy = vy * inv, uz = vz * inv;
    const float SQ3 = 1.7320508075688772f;
    const float SQ5 = 2.2360679774997896f;
    const float SQ15 = 3.8729833462074170f;
    float sh1 = SQ3 * ux, sh2 = SQ3 * uy, sh3 = SQ3 * uz;
    float sh4 = SQ15 * ux * uz;
    float sh5 = SQ15 * ux * uy;
    float sh6 = SQ5 * (uy * uy - 0.5f * (ux * ux + uz * uz));
    float sh7 = SQ15 * uy * uz;
    float sh8 = 0.5f * SQ15 * (uz * uz - ux * ux);
    float d = r * 0.1f;
    float d2 = d * d;
    float d5 = d2 * d2 * d;
    float fc = 1.f + d5 * (-21.f + d * (35.f - 15.f * d));
    fc = (d < 1.f) ? fc : 0.f;
    float ee = __expf(-d2) * fc;
    float g0 = ee, g1 = d * ee, g2 = d2 * ee;

    const float4* xp = (const float4*)(g_xp + 12 * (size_t)s);
    float4 xa = xp[0], xb = xp[1];
    float x8 = g_xp[12 * (size_t)s + 8];

    float* ga = g_a + 12 * (size_t)t;
    float m0 = xa.x * g0;
    float m1 = xa.y * sh1 * g1;
    float m2 = xa.z * sh2 * g1;
    float m3 = xa.w * sh3 * g1;
    float m4 = xb.x * sh4 * g2;
    float m5 = xb.y * sh5 * g2;
    float m6 = xb.z * sh6 * g2;
    float m7 = xb.w * sh7 * g2;
    float m8 = x8   * sh8 * g2;
    asm volatile("red.global.add.v4.f32 [%0], {%1,%2,%3,%4};"
                 :: "l"(ga), "f"(m0), "f"(m1), "f"(m2), "f"(m3) : "memory");
    asm volatile("red.global.add.v4.f32 [%0], {%1,%2,%3,%4};"
                 :: "l"(ga + 4), "f"(m4), "f"(m5), "f"(m6), "f"(m7) : "memory");
    atomicAdd(ga + 8, m8);

    // erbf via sin recurrence -> smem (stride 17)
    float sp, cp;
    __sincosf(0.31415926535897931f * r, &sp, &cp);
    float coef = 0.44721359549995793f * inv * fc;
    float* rb = s_rbf + tid * 17;
    float sprev = 0.f, scur = sp;
    float twoc = 2.f * cp;
#pragma unroll
    for (int n = 0; n < 16; n++) {
        rb[n] = coef * scur;
        float nx = twoc * scur - sprev;
        sprev = scur; scur = nx;
    }
    float* es = s_sh9 + tid * 9;
    es[0] = 1.f;
    es[1] = -sh1; es[2] = -sh2; es[3] = -sh3;
    es[4] = sh4; es[5] = sh5; es[6] = sh6; es[7] = sh7; es[8] = sh8;
    __syncthreads();

    // coalesced scalar writeout
    float* eb = erbf + (size_t)e0 * 16;
#pragma unroll
    for (int i = 0; i < 16; i++) {
        int j = tid + 256 * i;
        eb[j] = s_rbf[(j >> 4) * 17 + (j & 15)];
    }
    float* ep = ersh + (size_t)e0 * 9;
#pragma unroll
    for (int i = 0; i < 9; i++) {
        int j = tid + 256 * i;
        ep[j] = s_sh9[j];
    }
}

// ---------------- node kernel ----------------
#define SM_W0A   0        // 384
#define SM_W1A   384      // 256
#define SM_W2A   640      // 128
#define SM_W0B   768      // 16384 [k][f]
#define SM_W1B   17152    // 4096  [u][v]
#define SM_W2B   21248    // 1024  [u][v]
#define SM_TPW   22272    // 12
#define SM_C112  22284    // 48
#define SM_W222  22332    // 128
#define SM_S     22460    // 32*13 = 416
#define SM_OUTT  22876    // 35*32 = 1120
#define SM_H0    23996    // 128*32 = 4096
#define SM_H1    28092    // 192*32 = 6144
#define SM_H2    34236    // 160*32 = 5120
#define SM_OUT   39360    // 480*33 = 15840 (16B aligned base)
#define SMEM_FLOATS 55200
#define SMEM_BYTES (SMEM_FLOATS * 4)

// stage B inner: 16 output feats, K-dim dot, feat pairs ride the f32x2 lanes
template<int K, int WS, int AS>
__device__ __forceinline__ void taskB(const float* __restrict__ ap,
                                      const ulonglong2* __restrict__ wp,
                                      float* __restrict__ f)
{
    ull acc[8];
#pragma unroll
    for (int j = 0; j < 8; j++) acc[j] = 0;
#pragma unroll 4
    for (int u = 0; u < K; u++) {
        float a = ap[u * AS];
        ull a2 = pack2(a, a);
        ulonglong2 q0 = wp[u * WS], q1 = wp[u * WS + 1];
        ulonglong2 q2 = wp[u * WS + 2], q3 = wp[u * WS + 3];
        fma2(acc[0], a2, q0.x); fma2(acc[1], a2, q0.y);
        fma2(acc[2], a2, q1.x); fma2(acc[3], a2, q1.y);
        fma2(acc[4], a2, q2.x); fma2(acc[5], a2, q2.y);
        fma2(acc[6], a2, q3.x); fma2(acc[7], a2, q3.y);
    }
#pragma unroll
    for (int j = 0; j < 8; j++) unpack2(acc[j], f[2 * j], f[2 * j + 1]);
}

__global__ void __launch_bounds__(512) k_node(
    const float* __restrict__ tp_w,
    const float* __restrict__ W0a, const float* __restrict__ W1a, const float* __restrict__ W2a,
    const float* __restrict__ W0b, const float* __restrict__ W1b, const float* __restrict__ W2b,
    float* __restrict__ out)
{
    extern __shared__ float sm[];
    float* w0a  = sm + SM_W0A;
    float* w1a  = sm + SM_W1A;
    float* w2a  = sm + SM_W2A;
    float* w0b  = sm + SM_W0B;
    float* w1b  = sm + SM_W1B;
    float* w2b  = sm + SM_W2B;
    float* tpw  = sm + SM_TPW;
    float* c112 = sm + SM_C112;
    float* w222 = sm + SM_W222;
    float* s_sh = sm + SM_S;     // stride 13 per node
    float* out_t = sm + SM_OUTT; // [q][32]
    float* h0aT = sm + SM_H0;    // [k][32]
    float* h1aT = sm + SM_H1;    // [(u*3+m)][32]
    float* h2aT = sm + SM_H2;    // [(u*5+m)][32]
    float* s_out = sm + SM_OUT;  // [f][33]

    const int tid = threadIdx.x;
    const int wid = tid >> 5;
    const int lane = tid & 31;

    for (int i = tid; i < 384; i += 512) w0a[i] = W0a[i];
    if (tid < 256) w1a[tid] = W1a[tid];
    if (tid >= 256 && tid < 384) w2a[tid - 256] = W2a[tid - 256];
    for (int i = tid; i < 16384; i += 512) w0b[i] = W0b[i];
    for (int i = tid; i < 4096;  i += 512) w1b[i] = W1b[i];
    for (int i = tid; i < 1024;  i += 512) w2b[i] = W2b[i];
    if (tid < 11)  tpw[tid]  = tp_w[tid];
    if (tid >= 32 && tid < 77)  c112[tid - 32] = g_C112[tid - 32];
    if (tid >= 128 && tid < 253) w222[tid - 128] = g_W222[tid - 128];
    __syncthreads();

    // running stats: 2 rounds x 16 feats
    float sq[2][16];
    float sm0[16];
#pragma unroll
    for (int k = 0; k < 2; k++)
#pragma unroll
        for (int j = 0; j < 16; j++) sq[k][j] = 0.f;
#pragma unroll
    for (int j = 0; j < 16; j++) sm0[j] = 0.f;

    for (int tile = blockIdx.x; tile < NTILES; tile += gridDim.x) {
        const int n0 = tile * 32;

        if (tid < 96) {
            int n = tid / 3;
            int c = tid - 3 * n;
            const float4* gp = (const float4*)(g_a + (size_t)(n0 + n) * 12);
            float4 v = gp[c];
            float* dst = s_sh + n * 13 + c * 4;
            dst[0] = v.x; dst[1] = v.y; dst[2] = v.z; dst[3] = v.w;
        }
        __syncthreads();

        // ---- tensor products: lane = node (cached s in regs), warp covers q = wid, wid+16, wid+32
        {
            float s[9];
#pragma unroll
            for (int i = 0; i < 9; i++) s[i] = s_sh[lane * 13 + i];
#pragma unroll
            for (int kq = 0; kq < 3; kq++) {
                int q = wid + 16 * kq;
                if (q >= 35) continue;
                float val;
                if (q == 0) {
                    val = tpw[0] * s[0] * s[0];
                } else if (q == 1) {
                    float a = s[1] * s[1] + s[2] * s[2] + s[3] * s[3];
                    val = tpw[1] * a * 0.57735026918962573f;
                } else if (q == 2) {
                    float a = 0.f;
#pragma unroll
                    for (int m = 0; m < 5; m++) a = fmaf(s[4 + m], s[4 + m], a);
                    val = tpw[2] * a * 0.44721359549995793f;
                } else if (q < 6) {
                    val = tpw[3] * s[0] * s[1 + (q - 3)];
                } else if (q < 9) {
                    val = tpw[4] * s[1 + (q - 6)] * s[0];
                } else if (q < 12) {
                    int j = q - 9; float a = 0.f;
#pragma unroll
                    for (int i = 0; i < 3; i++)
#pragma unroll
                        for (int m = 0; m < 5; m++)
                            a = fmaf(c112[i * 15 + j * 5 + m], s[1 + i] * s[4 + m], a);
                    val = tpw[5] * a;
                } else if (q < 15) {
                    int i = q - 12; float a = 0.f;
#pragma unroll
                    for (int j = 0; j < 3; j++)
#pragma unroll
                        for (int m = 0; m < 5; m++)
                            a = fmaf(c112[i * 15 + j * 5 + m], s[1 + j] * s[4 + m], a);
                    val = tpw[6] * a;
                } else if (q < 20) {
                    val = tpw[7] * s[0] * s[4 + (q - 15)];
                } else if (q < 25) {
                    val = tpw[8] * s[4 + (q - 20)] * s[0];
                } else if (q < 30) {
                    int m = q - 25; float a = 0.f;
#pragma unroll
                    for (int i = 0; i < 3; i++)
#pragma unroll
                        for (int j = 0; j < 3; j++)
                            a = fmaf(c112[i * 15 + j * 5 + m], s[1 + i] * s[1 + j], a);
                    val = tpw[9] * a;
                } else {
                    int c = q - 30; float a = 0.f;
#pragma unroll
                    for (int aa = 0; aa < 5; aa++)
#pragma unroll
                        for (int bb = 0; bb < 5; bb++)
                            a = fmaf(w222[(aa * 5 + bb) * 5 + c], s[4 + aa] * s[4 + bb], a);
                    val = tpw[10] * a;
                }
                out_t[q * 32 + lane] = val;
            }
        }
        __syncthreads();

        // ---- stage A: lane = node, acts cached in regs across v iterations
        {
            float o0 = out_t[lane], o1 = out_t[32 + lane], o2 = out_t[64 + lane];
#pragma unroll
            for (int k = 0; k < 8; k++) {
                int f = wid + 16 * k;
                float hv = o0 * w0a[f] + o1 * w0a[128 + f] + o2 * w0a[256 + f];
                h0aT[f * 32 + lane] = fsigmoid(hv);
            }
            float b1[12];
#pragma unroll
            for (int i = 0; i < 12; i++) b1[i] = out_t[(3 + i) * 32 + lane];
#pragma unroll
            for (int k = 0; k < 4; k++) {
                int v = wid + 16 * k;
                float m0 = 0.f, m1 = 0.f, m2 = 0.f;
#pragma unroll
                for (int u = 0; u < 4; u++) {
                    float w = w1a[u * 64 + v];
                    m0 = fmaf(b1[u * 3 + 0], w, m0);
                    m1 = fmaf(b1[u * 3 + 1], w, m1);
                    m2 = fmaf(b1[u * 3 + 2], w, m2);
                }
                float gt = fsigmoid(sqrtf(m0 * m0 + m1 * m1 + m2 * m2));
                h1aT[(v * 3 + 0) * 32 + lane] = m0 * gt;
                h1aT[(v * 3 + 1) * 32 + lane] = m1 * gt;
                h1aT[(v * 3 + 2) * 32 + lane] = m2 * gt;
            }
            float b2[20];
#pragma unroll
            for (int i = 0; i < 20; i++) b2[i] = out_t[(15 + i) * 32 + lane];
#pragma unroll
            for (int k = 0; k < 2; k++) {
                int v = wid + 16 * k;
                float m[5] = {0.f, 0.f, 0.f, 0.f, 0.f};
#pragma unroll
                for (int u = 0; u < 4; u++) {
                    float w = w2a[u * 32 + v];
#pragma unroll
                    for (int mm = 0; mm < 5; mm++)
                        m[mm] = fmaf(b2[u * 5 + mm], w, m[mm]);
                }
                float nrm = m[0]*m[0] + m[1]*m[1] + m[2]*m[2] + m[3]*m[3] + m[4]*m[4];
                float gt = fsigmoid(sqrtf(nrm));
#pragma unroll
                for (int mm = 0; mm < 5; mm++) h2aT[(v * 5 + mm) * 32 + lane] = m[mm] * gt;
            }
        }
        __syncthreads();

        // ---- stage B: 30 tasks x 16 feats, 2 rounds
#pragma unroll
        for (int k8 = 0; k8 < 2; k8++) {
            const int t = wid + 16 * k8;
            if (t >= 30) continue;
            float f[16];
            if (t < 8) {
                taskB<128, 32, 32>(h0aT + lane, (const ulonglong2*)w0b + 4 * t, f);
#pragma unroll
                for (int j = 0; j < 16; j++) {
                    s_out[(16 * t + j) * 33 + lane] = f[j];
                    sm0[j] += f[j];
                    sq[k8][j] = fmaf(f[j], f[j], sq[k8][j]);
                }
            } else if (t < 20) {
                const int idx = t - 8, m = idx >> 2, vg = idx & 3;
                taskB<64, 16, 96>(h1aT + m * 32 + lane, (const ulonglong2*)w1b + 4 * vg, f);
#pragma unroll
                for (int j = 0; j < 16; j++) {
                    s_out[(128 + (16 * vg + j) * 3 + m) * 33 + lane] = f[j];
                    sq[k8][j] = fmaf(f[j], f[j], sq[k8][j]);
                }
            } else {
                const int idx = t - 20, m = idx >> 1, vg = idx & 1;
                taskB<32, 8, 160>(h2aT + m * 32 + lane, (const ulonglong2*)w2b + 4 * vg, f);
#pragma unroll
                for (int j = 0; j < 16; j++) {
                    s_out[(320 + (16 * vg + j) * 5 + m) * 33 + lane] = f[j];
                    sq[k8][j] = fmaf(f[j], f[j], sq[k8][j]);
                }
            }
        }
        __syncthreads();

        // coalesced writeback
        if (tid < 480) {
            float* ob = out + (size_t)n0 * 480 + tid;
#pragma unroll 8
            for (int n = 0; n < 32; n++)
                ob[(size_t)n * 480] = s_out[tid * 33 + n];
        }
        __syncthreads();
    }

    // flush stats
#pragma unroll
    for (int k8 = 0; k8 < 2; k8++) {
        const int t = wid + 16 * k8;
        if (t >= 30) continue;
#pragma unroll
        for (int j = 0; j < 16; j++) {
            float v = sq[k8][j];
#pragma unroll
            for (int off = 16; off; off >>= 1) v += __shfl_xor_sync(0xffffffffu, v, off);
            if (lane == 0) {
                if (t < 8) atomicAdd(&g_h0sq[16 * t + j], v);
                else if (t < 20) { int idx = t - 8, m = idx >> 2, vg = idx & 3; atomicAdd(&g_h1sq[(16 * vg + j) * 3 + m], v); }
                else { int idx = t - 20, m = idx >> 1, vg = idx & 1; atomicAdd(&g_h2sq[(16 * vg + j) * 5 + m], v); }
            }
            if (t < 8) {
                float u2 = sm0[j];
#pragma unroll
                for (int off = 16; off; off >>= 1) u2 += __shfl_xor_sync(0xffffffffu, u2, off);
                if (lane == 0) atomicAdd(&g_h0sum[16 * t + j], u2);
            }
        }
    }
}

// ---------------- scale/bias precompute ----------------
__global__ void k_scale() {
    int t = threadIdx.x;
    const float invN = 1.f / (float)NN;
    const float EPS = 1e-5f;
    if (t < 128) {
        float mean = g_h0sum[t] * invN;
        float var = g_h0sq[t] * invN - mean * mean;
        float sc = rsqrtf(var + EPS);
        g_scale[t] = sc;
        g_bias[t] = -mean * sc;
    } else if (t < 320) {
        int o = t - 128; int v = o / 3;
        float ms = (g_h1sq[3 * v] + g_h1sq[3 * v + 1] + g_h1sq[3 * v + 2]) * invN * (1.f / 3.f);
        g_scale[t] = rsqrtf(ms + EPS);
        g_bias[t] = 0.f;
    } else if (t < 480) {
        int o = t - 320; int v = o / 5;
        float ms = (g_h2sq[5 * v] + g_h2sq[5 * v + 1] + g_h2sq[5 * v + 2] +
                    g_h2sq[5 * v + 3] + g_h2sq[5 * v + 4]) * invN * 0.2f;
        g_scale[t] = rsqrtf(ms + EPS);
        g_bias[t] = 0.f;
    }
}

// ---------------- normalize node output in place ----------------
__global__ void __launch_bounds__(128) k_norm(float* __restrict__ out) {
    int t = threadIdx.x;
    if (t >= 120) return;
    float4 sc = *(const float4*)(g_scale + 4 * t);
    float4 bs = *(const float4*)(g_bias + 4 * t);
    for (int n = blockIdx.x; n < NN; n += gridDim.x) {
        float4* p = (float4*)(out + (size_t)n * 480) + t;
        float4 v = *p;
        v.x = fmaf(v.x, sc.x, bs.x);
        v.y = fmaf(v.y, sc.y, bs.y);
        v.z = fmaf(v.z, sc.z, bs.z);
        v.w = fmaf(v.w, sc.w, bs.w);
        *p = v;
    }
}

// ---------------- launch ----------------
extern "C" void kernel_launch(void* const* d_in, const int* in_sizes, int n_in,
                              void* d_out, int out_size) {
    const float* x   = (const float*)d_in[0];
    const float* pos = (const float*)d_in[1];
    const int*   ei  = (const int*)d_in[2];
    const float* tpw = (const float*)d_in[3];
    const float* W0a = (const float*)d_in[4];
    const float* W1a = (const float*)d_in[5];
    const float* W2a = (const float*)d_in[6];
    const float* W0b = (const float*)d_in[7];
    const float* W1b = (const float*)d_in[8];
    const float* W2b = (const float*)d_in[9];

    float* out  = (float*)d_out;
    float* erbf = out + (size_t)NN * 480;
    float* ersh = erbf + (size_t)NE * 16;

    cudaFuncSetAttribute(k_node, cudaFuncAttributeMaxDynamicSharedMemorySize, SMEM_BYTES);

    k_init<<<1, 32>>>();
    k_prep<<<(NN + 255) / 256, 256>>>(x, pos);
    k_edge<<<NE / 256, 256>>>(ei, erbf, ersh);
    k_node<<<148, 512, SMEM_BYTES>>>(tpw, W0a, W1a, W2a, W0b, W1b, W2b, out);
    k_scale<<<1, 512>>>();
    k_norm<<<1184, 128>>>(out);
}

// round 6
// speedup vs baseline: 2.7692x; 1.0066x over previous
#include <cuda_runtime.h>
#include <math.h>
#include <stdint.h>

#define NN 100000
#define NN2 100032          // padded to multiple of 64
#define NE 3200000
#define NT64 1563           // ceil(NN / 64)

typedef unsigned long long ull;

// ---------------- device scratch ----------------
__device__ float g_a[NN2 * 12];        // segment sums, padded stride 12
__device__ float g_xp[NN * 12];        // padded x
__device__ float4 g_pos4[NN];          // permuted pos
__device__ float g_outT[480 * (size_t)NN2];  // transposed staging [feat][node]
__device__ float g_C112[45];
__device__ float g_W222[125];
__device__ float g_h0sum[128];
__device__ float g_h0sq[128];
__device__ float g_h1sq[192];
__device__ float g_h2sq[160];
__device__ __align__(16) float g_scale[480];
__device__ __align__(16) float g_bias[480];

__device__ __forceinline__ float fsigmoid(float x) {
    return __fdividef(1.f, 1.f + __expf(-x));
}
__device__ __forceinline__ ull pack2(float a, float b) {
    ull r; asm("mov.b64 %0, {%1,%2};" : "=l"(r) : "f"(a), "f"(b)); return r;
}
__device__ __forceinline__ void fma2(ull& d, ull a, ull b) {
    asm("fma.rn.f32x2 %0, %1, %2, %0;" : "+l"(d) : "l"(a), "l"(b));
}
__device__ __forceinline__ void unpack2(ull v, float& a, float& b) {
    asm("mov.b64 {%0,%1}, %2;" : "=f"(a), "=f"(b) : "l"(v));
}

// ---------------- constant tensors ----------------
__global__ void k_init() {
    if (threadIdx.x != 0 || blockIdx.x != 0) return;
    float A[5][3][3];
    for (int m = 0; m < 5; m++)
        for (int i = 0; i < 3; i++)
            for (int j = 0; j < 3; j++) A[m][i][j] = 0.f;
    const float h = sqrtf(15.f) * 0.5f;
    const float s5 = sqrtf(5.f);
    A[0][0][2] = h; A[0][2][0] = h;
    A[1][0][1] = h; A[1][1][0] = h;
    A[2][0][0] = -0.5f * s5; A[2][1][1] = s5; A[2][2][2] = -0.5f * s5;
    A[3][1][2] = h; A[3][2][1] = h;
    A[4][0][0] = -h; A[4][2][2] = h;
    float ss = 0.f;
    for (int m = 0; m < 5; m++)
        for (int i = 0; i < 3; i++)
            for (int j = 0; j < 3; j++) ss += A[m][i][j] * A[m][i][j];
    float inv = 1.f / sqrtf(ss);
    for (int i = 0; i < 3; i++)
        for (int j = 0; j < 3; j++)
            for (int m = 0; m < 5; m++)
                g_C112[i * 15 + j * 5 + m] = A[m][i][j] * inv;
    float Ws[5][5][5];
    float ss2 = 0.f;
    for (int m = 0; m < 5; m++)
        for (int n = 0; n < 5; n++)
            for (int p = 0; p < 5; p++) {
                float acc = 0.f, acc2 = 0.f;
                for (int i = 0; i < 3; i++)
                    for (int k = 0; k < 3; k++)
                        for (int j = 0; j < 3; j++) {
                            acc  += A[m][i][k] * A[n][k][j] * A[p][j][i];
                            acc2 += A[n][i][k] * A[m][k][j] * A[p][j][i];
                        }
                Ws[m][n][p] = acc + acc2;
                ss2 += (acc + acc2) * (acc + acc2);
            }
    float inv2 = 1.f / sqrtf(ss2);
    for (int m = 0; m < 5; m++)
        for (int n = 0; n < 5; n++)
            for (int p = 0; p < 5; p++)
                g_W222[(m * 5 + n) * 5 + p] = Ws[m][n][p] * inv2;
}

// ---------------- prep: pad x, permute pos, zero scratch ----------------
__global__ void k_prep(const float* __restrict__ x, const float* __restrict__ pos) {
    int n = blockIdx.x * blockDim.x + threadIdx.x;
    if (n < NN2) {
        float4 z = make_float4(0.f, 0.f, 0.f, 0.f);
        float4* ga = (float4*)(g_a + 12 * (size_t)n);
        ga[0] = z; ga[1] = z; ga[2] = z;
    }
    if (n < NN) {
        float4 p;
        p.x = pos[3 * n + 1]; p.y = pos[3 * n + 2]; p.z = pos[3 * n + 0]; p.w = 0.f;
        g_pos4[n] = p;
        const float* xs = x + 9 * (size_t)n;
        float4* xp = (float4*)(g_xp + 12 * (size_t)n);
        xp[0] = make_float4(xs[0], xs[1], xs[2], xs[3]);
        xp[1] = make_float4(xs[4], xs[5], xs[6], xs[7]);
        xp[2] = make_float4(xs[8], 0.f, 0.f, 0.f);
    }
}

// ---------------- edge kernel ----------------
__global__ void __launch_bounds__(256) k_edge(
    const int* __restrict__ ei,
    float* __restrict__ erbf, float* __restrict__ ersh)
{
    __shared__ float s_rbf[256 * 17];
    __shared__ float s_sh9[256 * 9];
    const int tid = threadIdx.x;
    const int e0 = blockIdx.x * 256;
    const int e = e0 + tid;

    int s = ei[e];
    int t = ei[NE + e];
    float4 ps = g_pos4[s], pt = g_pos4[t];
    float vx = pt.x - ps.x, vy = pt.y - ps.y, vz = pt.z - ps.z;
    float r2 = vx * vx + vy * vy + vz * vz;
    float r = sqrtf(r2);
    float inv = __fdividef(1.f, fmaxf(r, 1e-12f));
    float ux = vx * inv, uy = vy * inv, uz = vz * inv;
    const float SQ3 = 1.7320508075688772f;
    const float SQ5 = 2.2360679774997896f;
    const float SQ15 = 3.8729833462074170f;
    float sh1 = SQ3 * ux, sh2 = SQ3 * uy, sh3 = SQ3 * uz;
    float sh4 = SQ15 * ux * uz;
    float sh5 = SQ15 * ux * uy;
    float sh6 = SQ5 * (uy * uy - 0.5f * (ux * ux + uz * uz));
    float sh7 = SQ15 * uy * uz;
    float sh8 = 0.5f * SQ15 * (uz * uz - ux * ux);
    float d = r * 0.1f;
    float d2 = d * d;
    float d5 = d2 * d2 * d;
    float fc = 1.f + d5 * (-21.f + d * (35.f - 15.f * d));
    fc = (d < 1.f) ? fc : 0.f;
    float ee = __expf(-d2) * fc;
    float g0 = ee, g1 = d * ee, g2 = d2 * ee;

    const float4* xp = (const float4*)(g_xp + 12 * (size_t)s);
    float4 xa = xp[0], xb = xp[1];
    float x8 = g_xp[12 * (size_t)s + 8];

    float* ga = g_a + 12 * (size_t)t;
    float m0 = xa.x * g0;
    float m1 = xa.y * sh1 * g1;
    float m2 = xa.z * sh2 * g1;
    float m3 = xa.w * sh3 * g1;
    float m4 = xb.x * sh4 * g2;
    float m5 = xb.y * sh5 * g2;
    float m6 = xb.z * sh6 * g2;
    float m7 = xb.w * sh7 * g2;
    float m8 = x8   * sh8 * g2;
    asm volatile("red.global.add.v4.f32 [%0], {%1,%2,%3,%4};"
                 :: "l"(ga), "f"(m0), "f"(m1), "f"(m2), "f"(m3) : "memory");
    asm volatile("red.global.add.v4.f32 [%0], {%1,%2,%3,%4};"
                 :: "l"(ga + 4), "f"(m4), "f"(m5), "f"(m6), "f"(m7) : "memory");
    atomicAdd(ga + 8, m8);

    float sp, cp;
    __sincosf(0.31415926535897931f * r, &sp, &cp);
    float coef = 0.44721359549995793f * inv * fc;
    float* rb = s_rbf + tid * 17;
    float sprev = 0.f, scur = sp;
    float twoc = 2.f * cp;
#pragma unroll
    for (int n = 0; n < 16; n++) {
        rb[n] = coef * scur;
        float nx = twoc * scur - sprev;
        sprev = scur; scur = nx;
    }
    float* es = s_sh9 + tid * 9;
    es[0] = 1.f;
    es[1] = -sh1; es[2] = -sh2; es[3] = -sh3;
    es[4] = sh4; es[5] = sh5; es[6] = sh6; es[7] = sh7; es[8] = sh8;
    __syncthreads();

    float* eb = erbf + (size_t)e0 * 16;
#pragma unroll
    for (int i = 0; i < 16; i++) {
        int j = tid + 256 * i;
        eb[j] = s_rbf[(j >> 4) * 17 + (j & 15)];
    }
    float* ep = ersh + (size_t)e0 * 9;
#pragma unroll
    for (int i = 0; i < 9; i++) {
        int j = tid + 256 * i;
        ep[j] = s_sh9[j];
    }
}

// ---------------- node kernel: 64-node tiles, direct transposed stores ----------------
#define SM_W0A   0        // 384
#define SM_W1A   384      // 256
#define SM_W2A   640      // 128
#define SM_W0B   768      // 16384 [k][f]
#define SM_W1B   17152    // 4096  [u][v]
#define SM_W2B   21248    // 1024  [u][v]
#define SM_TPW   22272    // 12
#define SM_C112  22284    // 48
#define SM_W222  22332    // 128
#define SM_S     22460    // 64*13 = 832
#define SM_OUTT  23292    // 35*64 = 2240
#define SM_H0    25532    // 128*64 = 8192
#define SM_H1    33724    // 192*64 = 12288
#define SM_H2    46012    // 160*64 = 10240
#define SMEM_FLOATS 56252
#define SMEM_BYTES (SMEM_FLOATS * 4)

// 16 output feats x 64 nodes (2 per lane); direct coalesced STG.64 to g_outT
template<int K, int WS, int AS>
__device__ __forceinline__ void taskB64(const float* __restrict__ ap,
                                        const ulonglong2* __restrict__ wp,
                                        float* __restrict__ op, size_t rstride)
{
    ull A[8], B[8];
#pragma unroll
    for (int j = 0; j < 8; j++) { A[j] = 0; B[j] = 0; }
#pragma unroll 4
    for (int u = 0; u < K; u++) {
        ull av = *(const ull*)(ap + u * AS);
        float a0, a1; unpack2(av, a0, a1);
        ull p0 = pack2(a0, a0), p1 = pack2(a1, a1);
        ulonglong2 q0 = wp[u * WS],     q1 = wp[u * WS + 1];
        ulonglong2 q2 = wp[u * WS + 2], q3 = wp[u * WS + 3];
        fma2(A[0], p0, q0.x); fma2(B[0], p1, q0.x);
        fma2(A[1], p0, q0.y); fma2(B[1], p1, q0.y);
        fma2(A[2], p0, q1.x); fma2(B[2], p1, q1.x);
        fma2(A[3], p0, q1.y); fma2(B[3], p1, q1.y);
        fma2(A[4], p0, q2.x); fma2(B[4], p1, q2.x);
        fma2(A[5], p0, q2.y); fma2(B[5], p1, q2.y);
        fma2(A[6], p0, q3.x); fma2(B[6], p1, q3.x);
        fma2(A[7], p0, q3.y); fma2(B[7], p1, q3.y);
    }
#pragma unroll
    for (int j = 0; j < 8; j++) {
        float a0, a1, b0, b1;
        unpack2(A[j], a0, a1);
        unpack2(B[j], b0, b1);
        *(ull*)(op + (size_t)(2 * j) * rstride)     = pack2(a0, b0);
        *(ull*)(op + (size_t)(2 * j + 1) * rstride) = pack2(a1, b1);
    }
}

__global__ void __launch_bounds__(512) k_node(
    const float* __restrict__ tp_w,
    const float* __restrict__ W0a, const float* __restrict__ W1a, const float* __restrict__ W2a,
    const float* __restrict__ W0b, const float* __restrict__ W1b, const float* __restrict__ W2b)
{
    extern __shared__ float sm[];
    float* w0a  = sm + SM_W0A;
    float* w1a  = sm + SM_W1A;
    float* w2a  = sm + SM_W2A;
    float* w0b  = sm + SM_W0B;
    float* w1b  = sm + SM_W1B;
    float* w2b  = sm + SM_W2B;
    float* tpw  = sm + SM_TPW;
    float* c112 = sm + SM_C112;
    float* w222 = sm + SM_W222;
    float* s_sh = sm + SM_S;     // stride 13 per node, 64 nodes
    float* out_t = sm + SM_OUTT; // [q][64]
    float* h0aT = sm + SM_H0;    // [k][64]
    float* h1aT = sm + SM_H1;    // [(u*3+m)][64]
    float* h2aT = sm + SM_H2;    // [(u*5+m)][64]

    const int tid = threadIdx.x;
    const int wid = tid >> 5;
    const int lane = tid & 31;

    for (int i = tid; i < 384; i += 512) w0a[i] = W0a[i];
    if (tid < 256) w1a[tid] = W1a[tid];
    if (tid >= 256 && tid < 384) w2a[tid - 256] = W2a[tid - 256];
    for (int i = tid; i < 16384; i += 512) w0b[i] = W0b[i];
    for (int i = tid; i < 4096;  i += 512) w1b[i] = W1b[i];
    for (int i = tid; i < 1024;  i += 512) w2b[i] = W2b[i];
    if (tid < 11)  tpw[tid]  = tp_w[tid];
    if (tid >= 32 && tid < 77)  c112[tid - 32] = g_C112[tid - 32];
    if (tid >= 128 && tid < 253) w222[tid - 128] = g_W222[tid - 128];
    __syncthreads();

    for (int tile = blockIdx.x; tile < NT64; tile += gridDim.x) {
        const int n0 = tile * 64;

        // load s for 64 nodes (3 float4 each)
        if (tid < 192) {
            int n = tid / 3;
            int c = tid - 3 * n;
            const float4* gp = (const float4*)(g_a + (size_t)(n0 + n) * 12);
            float4 v = gp[c];
            float* dst = s_sh + n * 13 + c * 4;
            dst[0] = v.x; dst[1] = v.y; dst[2] = v.z; dst[3] = v.w;
        }
        __syncthreads();

        // ---- tensor products + stage A, per node half (lane = node-in-half)
#pragma unroll
        for (int half = 0; half < 2; half++) {
            const int node = half * 32 + lane;
            float s[9];
#pragma unroll
            for (int i = 0; i < 9; i++) s[i] = s_sh[node * 13 + i];
#pragma unroll
            for (int kq = 0; kq < 3; kq++) {
                int q = wid + 16 * kq;
                if (q >= 35) continue;
                float val;
                if (q == 0) {
                    val = tpw[0] * s[0] * s[0];
                } else if (q == 1) {
                    float a = s[1] * s[1] + s[2] * s[2] + s[3] * s[3];
                    val = tpw[1] * a * 0.57735026918962573f;
                } else if (q == 2) {
                    float a = 0.f;
#pragma unroll
                    for (int m = 0; m < 5; m++) a = fmaf(s[4 + m], s[4 + m], a);
                    val = tpw[2] * a * 0.44721359549995793f;
                } else if (q < 6) {
                    val = tpw[3] * s[0] * s[1 + (q - 3)];
                } else if (q < 9) {
                    val = tpw[4] * s[1 + (q - 6)] * s[0];
                } else if (q < 12) {
                    int j = q - 9; float a = 0.f;
#pragma unroll
                    for (int i = 0; i < 3; i++)
#pragma unroll
                        for (int m = 0; m < 5; m++)
                            a = fmaf(c112[i * 15 + j * 5 + m], s[1 + i] * s[4 + m], a);
                    val = tpw[5] * a;
                } else if (q < 15) {
                    int i = q - 12; float a = 0.f;
#pragma unroll
                    for (int j = 0; j < 3; j++)
#pragma unroll
                        for (int m = 0; m < 5; m++)
                            a = fmaf(c112[i * 15 + j * 5 + m], s[1 + j] * s[4 + m], a);
                    val = tpw[6] * a;
                } else if (q < 20) {
                    val = tpw[7] * s[0] * s[4 + (q - 15)];
                } else if (q < 25) {
                    val = tpw[8] * s[4 + (q - 20)] * s[0];
                } else if (q < 30) {
                    int m = q - 25; float a = 0.f;
#pragma unroll
                    for (int i = 0; i < 3; i++)
#pragma unroll
                        for (int j = 0; j < 3; j++)
                            a = fmaf(c112[i * 15 + j * 5 + m], s[1 + i] * s[1 + j], a);
                    val = tpw[9] * a;
                } else {
                    int c = q - 30; float a = 0.f;
#pragma unroll
                    for (int aa = 0; aa < 5; aa++)
#pragma unroll
                        for (int bb = 0; bb < 5; bb++)
                            a = fmaf(w222[(aa * 5 + bb) * 5 + c], s[4 + aa] * s[4 + bb], a);
                    val = tpw[10] * a;
                }
                out_t[q * 64 + node] = val;
            }
        }
        __syncthreads();

#pragma unroll
        for (int half = 0; half < 2; half++) {
            const int node = half * 32 + lane;
            float o0 = out_t[node], o1 = out_t[64 + node], o2 = out_t[128 + node];
#pragma unroll
            for (int k = 0; k < 8; k++) {
                int f = wid + 16 * k;
                float hv = o0 * w0a[f] + o1 * w0a[128 + f] + o2 * w0a[256 + f];
                h0aT[f * 64 + node] = fsigmoid(hv);
            }
            float b1[12];
#pragma unroll
            for (int i = 0; i < 12; i++) b1[i] = out_t[(3 + i) * 64 + node];
#pragma unroll
            for (int k = 0; k < 4; k++) {
                int v = wid + 16 * k;
                float m0 = 0.f, m1 = 0.f, m2 = 0.f;
#pragma unroll
                for (int u = 0; u < 4; u++) {
                    float w = w1a[u * 64 + v];
                    m0 = fmaf(b1[u * 3 + 0], w, m0);
                    m1 = fmaf(b1[u * 3 + 1], w, m1);
                    m2 = fmaf(b1[u * 3 + 2], w, m2);
                }
                float gt = fsigmoid(sqrtf(m0 * m0 + m1 * m1 + m2 * m2));
                h1aT[(v * 3 + 0) * 64 + node] = m0 * gt;
                h1aT[(v * 3 + 1) * 64 + node] = m1 * gt;
                h1aT[(v * 3 + 2) * 64 + node] = m2 * gt;
            }
            float b2[20];
#pragma unroll
            for (int i = 0; i < 20; i++) b2[i] = out_t[(15 + i) * 64 + node];
#pragma unroll
            for (int k = 0; k < 2; k++) {
                int v = wid + 16 * k;
                float m[5] = {0.f, 0.f, 0.f, 0.f, 0.f};
#pragma unroll
                for (int u = 0; u < 4; u++) {
                    float w = w2a[u * 32 + v];
#pragma unroll
                    for (int mm = 0; mm < 5; mm++)
                        m[mm] = fmaf(b2[u * 5 + mm], w, m[mm]);
                }
                float nrm = m[0]*m[0] + m[1]*m[1] + m[2]*m[2] + m[3]*m[3] + m[4]*m[4];
                float gt = fsigmoid(sqrtf(nrm));
#pragma unroll
                for (int mm = 0; mm < 5; mm++) h2aT[(v * 5 + mm) * 64 + node] = m[mm] * gt;
            }
        }
        __syncthreads();

        // ---- stage B: 30 tasks x (16 feats x 64 nodes), 2 rounds
#pragma unroll
        for (int k8 = 0; k8 < 2; k8++) {
            const int t = wid + 16 * k8;
            if (t >= 30) continue;
            if (t < 8) {
                taskB64<128, 32, 64>(h0aT + 2 * lane,
                                     (const ulonglong2*)w0b + 4 * t,
                                     g_outT + (size_t)(16 * t) * NN2 + n0 + 2 * lane,
                                     (size_t)NN2);
            } else if (t < 20) {
                const int idx = t - 8, m = idx >> 2, vg = idx & 3;
                taskB64<64, 16, 192>(h1aT + m * 64 + 2 * lane,
                                     (const ulonglong2*)w1b + 4 * vg,
                                     g_outT + (size_t)(128 + 48 * vg + m) * NN2 + n0 + 2 * lane,
                                     (size_t)(3 * NN2));
            } else {
                const int idx = t - 20, m = idx >> 1, vg = idx & 1;
                taskB64<32, 8, 320>(h2aT + m * 64 + 2 * lane,
                                    (const ulonglong2*)w2b + 4 * vg,
                                    g_outT + (size_t)(320 + 80 * vg + m) * NN2 + n0 + 2 * lane,
                                    (size_t)(5 * NN2));
            }
        }
        __syncthreads();
    }
}

// ---------------- stats over g_outT rows ----------------
__global__ void __launch_bounds__(256) k_stats() {
    const int f = blockIdx.x;                 // 0..479
    const float* row = g_outT + (size_t)f * NN2;
    float s = 0.f, q = 0.f;
    for (int i = threadIdx.x; i < NN; i += 256) {
        float v = row[i];
        s += v; q = fmaf(v, v, q);
    }
    __shared__ float ss[8], qq[8];
    const int wid = threadIdx.x >> 5, lane = threadIdx.x & 31;
#pragma unroll
    for (int off = 16; off; off >>= 1) {
        s += __shfl_xor_sync(0xffffffffu, s, off);
        q += __shfl_xor_sync(0xffffffffu, q, off);
    }
    if (lane == 0) { ss[wid] = s; qq[wid] = q; }
    __syncthreads();
    if (threadIdx.x == 0) {
        float S = 0.f, Q = 0.f;
#pragma unroll
        for (int i = 0; i < 8; i++) { S += ss[i]; Q += qq[i]; }
        if (f < 128)      { g_h0sum[f] = S; g_h0sq[f] = Q; }
        else if (f < 320) { g_h1sq[f - 128] = Q; }
        else              { g_h2sq[f - 320] = Q; }
    }
}

// ---------------- scale/bias precompute ----------------
__global__ void k_scale() {
    int t = threadIdx.x;
    const float invN = 1.f / (float)NN;
    const float EPS = 1e-5f;
    if (t < 128) {
        float mean = g_h0sum[t] * invN;
        float var = g_h0sq[t] * invN - mean * mean;
        float sc = rsqrtf(var + EPS);
        g_scale[t] = sc;
        g_bias[t] = -mean * sc;
    } else if (t < 320) {
        int o = t - 128; int v = o / 3;
        float ms = (g_h1sq[3 * v] + g_h1sq[3 * v + 1] + g_h1sq[3 * v + 2]) * invN * (1.f / 3.f);
        g_scale[t] = rsqrtf(ms + EPS);
        g_bias[t] = 0.f;
    } else if (t < 480) {
        int o = t - 320; int v = o / 5;
        float ms = (g_h2sq[5 * v] + g_h2sq[5 * v + 1] + g_h2sq[5 * v + 2] +
                    g_h2sq[5 * v + 3] + g_h2sq[5 * v + 4]) * invN * 0.2f;
        g_scale[t] = rsqrtf(ms + EPS);
        g_bias[t] = 0.f;
    }
}

// ---------------- normalize + transpose to final layout ----------------
__global__ void __launch_bounds__(512) k_norm(float* __restrict__ out) {
    __shared__ float ts[32 * 481];
    const int n0 = blockIdx.x * 32;
    for (int idx = threadIdx.x; idx < 480 * 32; idx += 512) {
        int f = idx >> 5, n = idx & 31;
        float v = g_outT[(size_t)f * NN2 + n0 + n];
        ts[n * 481 + f] = fmaf(v, g_scale[f], g_bias[f]);
    }
    __syncthreads();
    for (int idx = threadIdx.x; idx < 480 * 32; idx += 512) {
        int n = idx / 480, f = idx - n * 480;
        out[(size_t)(n0 + n) * 480 + f] = ts[n * 481 + f];
    }
}

// ---------------- launch ----------------
extern "C" void kernel_launch(void* const* d_in, const int* in_sizes, int n_in,
                              void* d_out, int out_size) {
    const float* x   = (const float*)d_in[0];
    const float* pos = (const float*)d_in[1];
    const int*   ei  = (const int*)d_in[2];
    const float* tpw = (const float*)d_in[3];
    const float* W0a = (const float*)d_in[4];
    const float* W1a = (const float*)d_in[5];
    const float* W2a = (const float*)d_in[6];
    const float* W0b = (const float*)d_in[7];
    const float* W1b = (const float*)d_in[8];
    const float* W2b = (const float*)d_in[9];

    float* out  = (float*)d_out;
    float* erbf = out + (size_t)NN * 480;
    float* ersh = erbf + (size_t)NE * 16;

    cudaFuncSetAttribute(k_node, cudaFuncAttributeMaxDynamicSharedMemorySize, SMEM_BYTES);

    k_init<<<1, 32>>>();
    k_prep<<<(NN2 + 255) / 256, 256>>>(x, pos);
    k_edge<<<NE / 256, 256>>>(ei, erbf, ersh);
    k_node<<<148, 512, SMEM_BYTES>>>(tpw, W0a, W1a, W2a, W0b, W1b, W2b);
    k_stats<<<480, 256>>>();
    k_scale<<<1, 512>>>();
    k_norm<<<NN / 32, 512>>>(out);
}

// round 7
// speedup vs baseline: 2.8958x; 1.0457x over previous
#include <cuda_runtime.h>
#include <math.h>
#include <stdint.h>

#define NN 100000
#define NN2 100032          // padded to multiple of 64
#define NE 3200000
#define NT64 1563           // ceil(NN / 64)

typedef unsigned long long ull;

// ---------------- device scratch ----------------
__device__ float g_a[NN2 * 12];        // segment sums, padded stride 12
__device__ float g_xp[NN * 12];        // padded x
__device__ float4 g_pos4[NN];          // permuted pos
__device__ float g_outT[480 * (size_t)NN2];  // transposed staging [feat][node]
__device__ float g_C112[45];
__device__ float g_W222[125];
__device__ float g_h0sum[128];
__device__ float g_h0sq[128];
__device__ float g_h1sq[192];
__device__ float g_h2sq[160];
__device__ __align__(16) float g_scale[480];
__device__ __align__(16) float g_bias[480];

__device__ __forceinline__ float fsigmoid(float x) {
    return __fdividef(1.f, 1.f + __expf(-x));
}
__device__ __forceinline__ ull pack2(float a, float b) {
    ull r; asm("mov.b64 %0, {%1,%2};" : "=l"(r) : "f"(a), "f"(b)); return r;
}
__device__ __forceinline__ void fma2(ull& d, ull a, ull b) {
    asm("fma.rn.f32x2 %0, %1, %2, %0;" : "+l"(d) : "l"(a), "l"(b));
}
__device__ __forceinline__ void unpack2(ull v, float& a, float& b) {
    asm("mov.b64 {%0,%1}, %2;" : "=f"(a), "=f"(b) : "l"(v));
}

// ---------------- constant tensors ----------------
__global__ void k_init() {
    if (threadIdx.x != 0 || blockIdx.x != 0) return;
    float A[5][3][3];
    for (int m = 0; m < 5; m++)
        for (int i = 0; i < 3; i++)
            for (int j = 0; j < 3; j++) A[m][i][j] = 0.f;
    const float h = sqrtf(15.f) * 0.5f;
    const float s5 = sqrtf(5.f);
    A[0][0][2] = h; A[0][2][0] = h;
    A[1][0][1] = h; A[1][1][0] = h;
    A[2][0][0] = -0.5f * s5; A[2][1][1] = s5; A[2][2][2] = -0.5f * s5;
    A[3][1][2] = h; A[3][2][1] = h;
    A[4][0][0] = -h; A[4][2][2] = h;
    float ss = 0.f;
    for (int m = 0; m < 5; m++)
        for (int i = 0; i < 3; i++)
            for (int j = 0; j < 3; j++) ss += A[m][i][j] * A[m][i][j];
    float inv = 1.f / sqrtf(ss);
    for (int i = 0; i < 3; i++)
        for (int j = 0; j < 3; j++)
            for (int m = 0; m < 5; m++)
                g_C112[i * 15 + j * 5 + m] = A[m][i][j] * inv;
    float Ws[5][5][5];
    float ss2 = 0.f;
    for (int m = 0; m < 5; m++)
        for (int n = 0; n < 5; n++)
            for (int p = 0; p < 5; p++) {
                float acc = 0.f, acc2 = 0.f;
                for (int i = 0; i < 3; i++)
                    for (int k = 0; k < 3; k++)
                        for (int j = 0; j < 3; j++) {
                            acc  += A[m][i][k] * A[n][k][j] * A[p][j][i];
                            acc2 += A[n][i][k] * A[m][k][j] * A[p][j][i];
                        }
                Ws[m][n][p] = acc + acc2;
                ss2 += (acc + acc2) * (acc + acc2);
            }
    float inv2 = 1.f / sqrtf(ss2);
    for (int m = 0; m < 5; m++)
        for (int n = 0; n < 5; n++)
            for (int p = 0; p < 5; p++)
                g_W222[(m * 5 + n) * 5 + p] = Ws[m][n][p] * inv2;
}

// ---------------- prep: pad x, permute pos, zero scratch ----------------
__global__ void k_prep(const float* __restrict__ x, const float* __restrict__ pos) {
    int n = blockIdx.x * blockDim.x + threadIdx.x;
    if (n < NN2) {
        float4 z = make_float4(0.f, 0.f, 0.f, 0.f);
        float4* ga = (float4*)(g_a + 12 * (size_t)n);
        ga[0] = z; ga[1] = z; ga[2] = z;
    }
    if (n < NN) {
        float4 p;
        p.x = pos[3 * n + 1]; p.y = pos[3 * n + 2]; p.z = pos[3 * n + 0]; p.w = 0.f;
        g_pos4[n] = p;
        const float* xs = x + 9 * (size_t)n;
        float4* xp = (float4*)(g_xp + 12 * (size_t)n);
        xp[0] = make_float4(xs[0], xs[1], xs[2], xs[3]);
        xp[1] = make_float4(xs[4], xs[5], xs[6], xs[7]);
        xp[2] = make_float4(xs[8], 0.f, 0.f, 0.f);
    }
}

// ---------------- edge kernel (column-major staging) ----------------
__global__ void __launch_bounds__(256) k_edge(
    const int* __restrict__ ei,
    float* __restrict__ erbf, float* __restrict__ ersh)
{
    __shared__ float s_rbf[16 * 257];   // [comp][edge], stride 257
    __shared__ float s_sh9[9 * 257];    // [comp][edge], stride 257
    const int tid = threadIdx.x;
    const int e0 = blockIdx.x * 256;
    const int e = e0 + tid;

    int s = ei[e];
    int t = ei[NE + e];
    float4 ps = g_pos4[s], pt = g_pos4[t];
    float vx = pt.x - ps.x, vy = pt.y - ps.y, vz = pt.z - ps.z;
    float r2 = vx * vx + vy * vy + vz * vz;
    float r = sqrtf(r2);
    float inv = __fdividef(1.f, fmaxf(r, 1e-12f));
    float ux = vx * inv, uy = vy * inv, uz = vz * inv;
    const float SQ3 = 1.7320508075688772f;
    const float SQ5 = 2.2360679774997896f;
    const float SQ15 = 3.8729833462074170f;
    float sh1 = SQ3 * ux, sh2 = SQ3 * uy, sh3 = SQ3 * uz;
    float sh4 = SQ15 * ux * uz;
    float sh5 = SQ15 * ux * uy;
    float sh6 = SQ5 * (uy * uy - 0.5f * (ux * ux + uz * uz));
    float sh7 = SQ15 * uy * uz;
    float sh8 = 0.5f * SQ15 * (uz * uz - ux * ux);
    float d = r * 0.1f;
    float d2 = d * d;
    float d5 = d2 * d2 * d;
    float fc = 1.f + d5 * (-21.f + d * (35.f - 15.f * d));
    fc = (d < 1.f) ? fc : 0.f;
    float ee = __expf(-d2) * fc;
    float g0 = ee, g1 = d * ee, g2 = d2 * ee;

    const float4* xp = (const float4*)(g_xp + 12 * (size_t)s);
    float4 xa = xp[0], xb = xp[1];
    float x8 = g_xp[12 * (size_t)s + 8];

    float* ga = g_a + 12 * (size_t)t;
    float m0 = xa.x * g0;
    float m1 = xa.y * sh1 * g1;
    float m2 = xa.z * sh2 * g1;
    float m3 = xa.w * sh3 * g1;
    float m4 = xb.x * sh4 * g2;
    float m5 = xb.y * sh5 * g2;
    float m6 = xb.z * sh6 * g2;
    float m7 = xb.w * sh7 * g2;
    float m8 = x8   * sh8 * g2;
    asm volatile("red.global.add.v4.f32 [%0], {%1,%2,%3,%4};"
                 :: "l"(ga), "f"(m0), "f"(m1), "f"(m2), "f"(m3) : "memory");
    asm volatile("red.global.add.v4.f32 [%0], {%1,%2,%3,%4};"
                 :: "l"(ga + 4), "f"(m4), "f"(m5), "f"(m6), "f"(m7) : "memory");
    atomicAdd(ga + 8, m8);

    // erbf via sin recurrence -> column-major smem (coalesced STS)
    float sp, cp;
    __sincosf(0.31415926535897931f * r, &sp, &cp);
    float coef = 0.44721359549995793f * inv * fc;
    float sprev = 0.f, scur = sp;
    float twoc = 2.f * cp;
#pragma unroll
    for (int n = 0; n < 16; n++) {
        s_rbf[n * 257 + tid] = coef * scur;
        float nx = twoc * scur - sprev;
        sprev = scur; scur = nx;
    }
    s_sh9[0 * 257 + tid] = 1.f;
    s_sh9[1 * 257 + tid] = -sh1;
    s_sh9[2 * 257 + tid] = -sh2;
    s_sh9[3 * 257 + tid] = -sh3;
    s_sh9[4 * 257 + tid] = sh4;
    s_sh9[5 * 257 + tid] = sh5;
    s_sh9[6 * 257 + tid] = sh6;
    s_sh9[7 * 257 + tid] = sh7;
    s_sh9[8 * 257 + tid] = sh8;
    __syncthreads();

    // coalesced writeout
    float* eb = erbf + (size_t)e0 * 16;
#pragma unroll
    for (int i = 0; i < 16; i++) {
        int j = tid + 256 * i;
        eb[j] = s_rbf[(j & 15) * 257 + (j >> 4)];
    }
    float* ep = ersh + (size_t)e0 * 9;
#pragma unroll
    for (int i = 0; i < 9; i++) {
        int j = tid + 256 * i;
        ep[j] = s_sh9[(j % 9) * 257 + j / 9];
    }
}

// ---------------- node kernel: 64-node tiles, direct transposed stores ----------------
#define SM_W0A   0        // 384
#define SM_W1A   384      // 256
#define SM_W2A   640      // 128
#define SM_W0B   768      // 16384 [k][f]
#define SM_W1B   17152    // 4096  [u][v]
#define SM_W2B   21248    // 1024  [u][v]
#define SM_TPW   22272    // 12
#define SM_C112  22284    // 48
#define SM_W222  22332    // 128
#define SM_S     22460    // 64*13 = 832
#define SM_OUTT  23292    // 35*64 = 2240
#define SM_H0    25532    // 128*64 = 8192
#define SM_H1    33724    // 192*64 = 12288
#define SM_H2    46012    // 160*64 = 10240
#define SMEM_FLOATS 56252
#define SMEM_BYTES (SMEM_FLOATS * 4)

template<int K, int WS, int AS>
__device__ __forceinline__ void taskB64(const float* __restrict__ ap,
                                        const ulonglong2* __restrict__ wp,
                                        float* __restrict__ op, size_t rstride)
{
    ull A[8], B[8];
#pragma unroll
    for (int j = 0; j < 8; j++) { A[j] = 0; B[j] = 0; }
#pragma unroll 4
    for (int u = 0; u < K; u++) {
        ull av = *(const ull*)(ap + u * AS);
        float a0, a1; unpack2(av, a0, a1);
        ull p0 = pack2(a0, a0), p1 = pack2(a1, a1);
        ulonglong2 q0 = wp[u * WS],     q1 = wp[u * WS + 1];
        ulonglong2 q2 = wp[u * WS + 2], q3 = wp[u * WS + 3];
        fma2(A[0], p0, q0.x); fma2(B[0], p1, q0.x);
        fma2(A[1], p0, q0.y); fma2(B[1], p1, q0.y);
        fma2(A[2], p0, q1.x); fma2(B[2], p1, q1.x);
        fma2(A[3], p0, q1.y); fma2(B[3], p1, q1.y);
        fma2(A[4], p0, q2.x); fma2(B[4], p1, q2.x);
        fma2(A[5], p0, q2.y); fma2(B[5], p1, q2.y);
        fma2(A[6], p0, q3.x); fma2(B[6], p1, q3.x);
        fma2(A[7], p0, q3.y); fma2(B[7], p1, q3.y);
    }
#pragma unroll
    for (int j = 0; j < 8; j++) {
        float a0, a1, b0, b1;
        unpack2(A[j], a0, a1);
        unpack2(B[j], b0, b1);
        *(ull*)(op + (size_t)(2 * j) * rstride)     = pack2(a0, b0);
        *(ull*)(op + (size_t)(2 * j + 1) * rstride) = pack2(a1, b1);
    }
}

__global__ void __launch_bounds__(512) k_node(
    const float* __restrict__ tp_w,
    const float* __restrict__ W0a, const float* __restrict__ W1a, const float* __restrict__ W2a,
    const float* __restrict__ W0b, const float* __restrict__ W1b, const float* __restrict__ W2b)
{
    extern __shared__ float sm[];
    float* w0a  = sm + SM_W0A;
    float* w1a  = sm + SM_W1A;
    float* w2a  = sm + SM_W2A;
    float* w0b  = sm + SM_W0B;
    float* w1b  = sm + SM_W1B;
    float* w2b  = sm + SM_W2B;
    float* tpw  = sm + SM_TPW;
    float* c112 = sm + SM_C112;
    float* w222 = sm + SM_W222;
    float* s_sh = sm + SM_S;
    float* out_t = sm + SM_OUTT;
    float* h0aT = sm + SM_H0;
    float* h1aT = sm + SM_H1;
    float* h2aT = sm + SM_H2;

    const int tid = threadIdx.x;
    const int wid = tid >> 5;
    const int lane = tid & 31;

    for (int i = tid; i < 384; i += 512) w0a[i] = W0a[i];
    if (tid < 256) w1a[tid] = W1a[tid];
    if (tid >= 256 && tid < 384) w2a[tid - 256] = W2a[tid - 256];
    for (int i = tid; i < 16384; i += 512) w0b[i] = W0b[i];
    for (int i = tid; i < 4096;  i += 512) w1b[i] = W1b[i];
    for (int i = tid; i < 1024;  i += 512) w2b[i] = W2b[i];
    if (tid < 11)  tpw[tid]  = tp_w[tid];
    if (tid >= 32 && tid < 77)  c112[tid - 32] = g_C112[tid - 32];
    if (tid >= 128 && tid < 253) w222[tid - 128] = g_W222[tid - 128];
    __syncthreads();

    for (int tile = blockIdx.x; tile < NT64; tile += gridDim.x) {
        const int n0 = tile * 64;

        if (tid < 192) {
            int n = tid / 3;
            int c = tid - 3 * n;
            const float4* gp = (const float4*)(g_a + (size_t)(n0 + n) * 12);
            float4 v = gp[c];
            float* dst = s_sh + n * 13 + c * 4;
            dst[0] = v.x; dst[1] = v.y; dst[2] = v.z; dst[3] = v.w;
        }
        __syncthreads();

#pragma unroll
        for (int half = 0; half < 2; half++) {
            const int node = half * 32 + lane;
            float s[9];
#pragma unroll
            for (int i = 0; i < 9; i++) s[i] = s_sh[node * 13 + i];
#pragma unroll
            for (int kq = 0; kq < 3; kq++) {
                int q = wid + 16 * kq;
                if (q >= 35) continue;
                float val;
                if (q == 0) {
                    val = tpw[0] * s[0] * s[0];
                } else if (q == 1) {
                    float a = s[1] * s[1] + s[2] * s[2] + s[3] * s[3];
                    val = tpw[1] * a * 0.57735026918962573f;
                } else if (q == 2) {
                    float a = 0.f;
#pragma unroll
                    for (int m = 0; m < 5; m++) a = fmaf(s[4 + m], s[4 + m], a);
                    val = tpw[2] * a * 0.44721359549995793f;
                } else if (q < 6) {
                    val = tpw[3] * s[0] * s[1 + (q - 3)];
                } else if (q < 9) {
                    val = tpw[4] * s[1 + (q - 6)] * s[0];
                } else if (q < 12) {
                    int j = q - 9; float a = 0.f;
#pragma unroll
                    for (int i = 0; i < 3; i++)
#pragma unroll
                        for (int m = 0; m < 5; m++)
                            a = fmaf(c112[i * 15 + j * 5 + m], s[1 + i] * s[4 + m], a);
                    val = tpw[5] * a;
                } else if (q < 15) {
                    int i = q - 12; float a = 0.f;
#pragma unroll
                    for (int j = 0; j < 3; j++)
#pragma unroll
                        for (int m = 0; m < 5; m++)
                            a = fmaf(c112[i * 15 + j * 5 + m], s[1 + j] * s[4 + m], a);
                    val = tpw[6] * a;
                } else if (q < 20) {
                    val = tpw[7] * s[0] * s[4 + (q - 15)];
                } else if (q < 25) {
                    val = tpw[8] * s[4 + (q - 20)] * s[0];
                } else if (q < 30) {
                    int m = q - 25; float a = 0.f;
#pragma unroll
                    for (int i = 0; i < 3; i++)
#pragma unroll
                        for (int j = 0; j < 3; j++)
                            a = fmaf(c112[i * 15 + j * 5 + m], s[1 + i] * s[1 + j], a);
                    val = tpw[9] * a;
                } else {
                    int c = q - 30; float a = 0.f;
#pragma unroll
                    for (int aa = 0; aa < 5; aa++)
#pragma unroll
                        for (int bb = 0; bb < 5; bb++)
                            a = fmaf(w222[(aa * 5 + bb) * 5 + c], s[4 + aa] * s[4 + bb], a);
                    val = tpw[10] * a;
                }
                out_t[q * 64 + node] = val;
            }
        }
        __syncthreads();

#pragma unroll
        for (int half = 0; half < 2; half++) {
            const int node = half * 32 + lane;
            float o0 = out_t[node], o1 = out_t[64 + node], o2 = out_t[128 + node];
#pragma unroll
            for (int k = 0; k < 8; k++) {
                int f = wid + 16 * k;
                float hv = o0 * w0a[f] + o1 * w0a[128 + f] + o2 * w0a[256 + f];
                h0aT[f * 64 + node] = fsigmoid(hv);
            }
            float b1[12];
#pragma unroll
            for (int i = 0; i < 12; i++) b1[i] = out_t[(3 + i) * 64 + node];
#pragma unroll
            for (int k = 0; k < 4; k++) {
                int v = wid + 16 * k;
                float m0 = 0.f, m1 = 0.f, m2 = 0.f;
#pragma unroll
                for (int u = 0; u < 4; u++) {
                    float w = w1a[u * 64 + v];
                    m0 = fmaf(b1[u * 3 + 0], w, m0);
                    m1 = fmaf(b1[u * 3 + 1], w, m1);
                    m2 = fmaf(b1[u * 3 + 2], w, m2);
                }
                float gt = fsigmoid(sqrtf(m0 * m0 + m1 * m1 + m2 * m2));
                h1aT[(v * 3 + 0) * 64 + node] = m0 * gt;
                h1aT[(v * 3 + 1) * 64 + node] = m1 * gt;
                h1aT[(v * 3 + 2) * 64 + node] = m2 * gt;
            }
            float b2[20];
#pragma unroll
            for (int i = 0; i < 20; i++) b2[i] = out_t[(15 + i) * 64 + node];
#pragma unroll
            for (int k = 0; k < 2; k++) {
                int v = wid + 16 * k;
                float m[5] = {0.f, 0.f, 0.f, 0.f, 0.f};
#pragma unroll
                for (int u = 0; u < 4; u++) {
                    float w = w2a[u * 32 + v];
#pragma unroll
                    for (int mm = 0; mm < 5; mm++)
                        m[mm] = fmaf(b2[u * 5 + mm], w, m[mm]);
                }
                float nrm = m[0]*m[0] + m[1]*m[1] + m[2]*m[2] + m[3]*m[3] + m[4]*m[4];
                float gt = fsigmoid(sqrtf(nrm));
#pragma unroll
                for (int mm = 0; mm < 5; mm++) h2aT[(v * 5 + mm) * 64 + node] = m[mm] * gt;
            }
        }
        __syncthreads();

#pragma unroll
        for (int k8 = 0; k8 < 2; k8++) {
            const int t = wid + 16 * k8;
            if (t >= 30) continue;
            if (t < 8) {
                taskB64<128, 32, 64>(h0aT + 2 * lane,
                                     (const ulonglong2*)w0b + 4 * t,
                                     g_outT + (size_t)(16 * t) * NN2 + n0 + 2 * lane,
                                     (size_t)NN2);
            } else if (t < 20) {
                const int idx = t - 8, m = idx >> 2, vg = idx & 3;
                taskB64<64, 16, 192>(h1aT + m * 64 + 2 * lane,
                                     (const ulonglong2*)w1b + 4 * vg,
                                     g_outT + (size_t)(128 + 48 * vg + m) * NN2 + n0 + 2 * lane,
                                     (size_t)(3 * NN2));
            } else {
                const int idx = t - 20, m = idx >> 1, vg = idx & 1;
                taskB64<32, 8, 320>(h2aT + m * 64 + 2 * lane,
                                    (const ulonglong2*)w2b + 4 * vg,
                                    g_outT + (size_t)(320 + 80 * vg + m) * NN2 + n0 + 2 * lane,
                                    (size_t)(5 * NN2));
            }
        }
        __syncthreads();
    }
}

// ---------------- stats over g_outT rows (float4) ----------------
__global__ void __launch_bounds__(256) k_stats() {
    const int f = blockIdx.x;                 // 0..479
    const float4* row = (const float4*)(g_outT + (size_t)f * NN2);
    float s = 0.f, q = 0.f;
    for (int i = threadIdx.x; i < 25000; i += 256) {
        float4 v = row[i];
        s += (v.x + v.y) + (v.z + v.w);
        q = fmaf(v.x, v.x, q); q = fmaf(v.y, v.y, q);
        q = fmaf(v.z, v.z, q); q = fmaf(v.w, v.w, q);
    }
    __shared__ float ss[8], qq[8];
    const int wid = threadIdx.x >> 5, lane = threadIdx.x & 31;
#pragma unroll
    for (int off = 16; off; off >>= 1) {
        s += __shfl_xor_sync(0xffffffffu, s, off);
        q += __shfl_xor_sync(0xffffffffu, q, off);
    }
    if (lane == 0) { ss[wid] = s; qq[wid] = q; }
    __syncthreads();
    if (threadIdx.x == 0) {
        float S = 0.f, Q = 0.f;
#pragma unroll
        for (int i = 0; i < 8; i++) { S += ss[i]; Q += qq[i]; }
        if (f < 128)      { g_h0sum[f] = S; g_h0sq[f] = Q; }
        else if (f < 320) { g_h1sq[f - 128] = Q; }
        else              { g_h2sq[f - 320] = Q; }
    }
}

// ---------------- scale/bias precompute ----------------
__global__ void k_scale() {
    int t = threadIdx.x;
    const float invN = 1.f / (float)NN;
    const float EPS = 1e-5f;
    if (t < 128) {
        float mean = g_h0sum[t] * invN;
        float var = g_h0sq[t] * invN - mean * mean;
        float sc = rsqrtf(var + EPS);
        g_scale[t] = sc;
        g_bias[t] = -mean * sc;
    } else if (t < 320) {
        int o = t - 128; int v = o / 3;
        float ms = (g_h1sq[3 * v] + g_h1sq[3 * v + 1] + g_h1sq[3 * v + 2]) * invN * (1.f / 3.f);
        g_scale[t] = rsqrtf(ms + EPS);
        g_bias[t] = 0.f;
    } else if (t < 480) {
        int o = t - 320; int v = o / 5;
        float ms = (g_h2sq[5 * v] + g_h2sq[5 * v + 1] + g_h2sq[5 * v + 2] +
                    g_h2sq[5 * v + 3] + g_h2sq[5 * v + 4]) * invN * 0.2f;
        g_scale[t] = rsqrtf(ms + EPS);
        g_bias[t] = 0.f;
    }
}

// ---------------- normalize + transpose to final layout (64-node tiles) ----------------
#define NORM_SMEM_BYTES (64 * 481 * 4)
__global__ void __launch_bounds__(512) k_norm(float* __restrict__ out) {
    extern __shared__ float ts[];   // [64][481]
    const int n0 = blockIdx.x * 64;
    const int tid = threadIdx.x;
    for (int idx = tid; idx < 480 * 16; idx += 512) {
        int f = idx >> 4, k = idx & 15;
        float4 v = *(const float4*)(g_outT + (size_t)f * NN2 + n0 + 4 * k);
        float sc = g_scale[f], bs = g_bias[f];
        ts[(4 * k + 0) * 481 + f] = fmaf(v.x, sc, bs);
        ts[(4 * k + 1) * 481 + f] = fmaf(v.y, sc, bs);
        ts[(4 * k + 2) * 481 + f] = fmaf(v.z, sc, bs);
        ts[(4 * k + 3) * 481 + f] = fmaf(v.w, sc, bs);
    }
    __syncthreads();
    for (int idx = tid; idx < 64 * 120; idx += 512) {
        int n = idx / 120, q = idx - n * 120;
        if (n0 + n < NN) {
            float4 v = make_float4(ts[n * 481 + 4 * q],     ts[n * 481 + 4 * q + 1],
                                   ts[n * 481 + 4 * q + 2], ts[n * 481 + 4 * q + 3]);
            *(float4*)(out + (size_t)(n0 + n) * 480 + 4 * q) = v;
        }
    }
}

// ---------------- launch ----------------
extern "C" void kernel_launch(void* const* d_in, const int* in_sizes, int n_in,
                              void* d_out, int out_size) {
    const float* x   = (const float*)d_in[0];
    const float* pos = (const float*)d_in[1];
    const int*   ei  = (const int*)d_in[2];
    const float* tpw = (const float*)d_in[3];
    const float* W0a = (const float*)d_in[4];
    const float* W1a = (const float*)d_in[5];
    const float* W2a = (const float*)d_in[6];
    const float* W0b = (const float*)d_in[7];
    const float* W1b = (const float*)d_in[8];
    const float* W2b = (const float*)d_in[9];

    float* out  = (float*)d_out;
    float* erbf = out + (size_t)NN * 480;
    float* ersh = erbf + (size_t)NE * 16;

    cudaFuncSetAttribute(k_node, cudaFuncAttributeMaxDynamicSharedMemorySize, SMEM_BYTES);
    cudaFuncSetAttribute(k_norm, cudaFuncAttributeMaxDynamicSharedMemorySize, NORM_SMEM_BYTES);

    k_init<<<1, 32>>>();
    k_prep<<<(NN2 + 255) / 256, 256>>>(x, pos);
    k_edge<<<NE / 256, 256>>>(ei, erbf, ersh);
    k_node<<<148, 512, SMEM_BYTES>>>(tpw, W0a, W1a, W2a, W0b, W1b, W2b);
    k_stats<<<480, 256>>>();
    k_scale<<<1, 512>>>();
    k_norm<<<NT64, 512, NORM_SMEM_BYTES>>>(out);
}